// round 9
// baseline (speedup 1.0000x reference)
#include <cuda_runtime.h>
#include <cuda_fp16.h>
#include <math.h>
#include <stdint.h>

#define B_  8
#define S_  1024
#define D_  768
#define H_  12
#define F_  3072
#define HD_ 64
#define M_  (B_*S_)   // 8192 rows

typedef __half hf;

// ---------------- scratch (device globals; no allocation allowed) ----------
__device__ __align__(16) hf g_x_h [(size_t)M_*D_];
__device__ __align__(16) hf g_W3h [3*D_*D_],         g_W3l [3*D_*D_];
__device__ __align__(16) hf g_qkv_h[(size_t)M_*3*D_], g_qkv_l[(size_t)M_*3*D_];
__device__ __align__(16) hf g_wv_h[(size_t)M_*D_];
__device__ __align__(16) hf g_ow_h[D_*D_],           g_ow_l[D_*D_];
__device__ __align__(16) hf g_ao_h[(size_t)M_*D_];
__device__ __align__(16) hf g_fc1_h[F_*D_],          g_fc1_l[F_*D_];
__device__ __align__(16) hf g_ff_h[(size_t)M_*F_];
__device__ __align__(16) hf g_fc2_h[D_*F_],          g_fc2_l[D_*F_];

#define SWZ(o) ((o) ^ (((o) >> 3) & 0x70))

// ---------------- primitives ------------------------------------------------
__device__ __forceinline__ uint32_t smem_u32(const void* p) {
    uint32_t a;
    asm("{ .reg .u64 t; cvta.to.shared.u64 t, %1; cvt.u32.u64 %0, t; }" : "=r"(a) : "l"(p));
    return a;
}
__device__ __forceinline__ void ldmx4(uint32_t addr, uint32_t& r0, uint32_t& r1,
                                      uint32_t& r2, uint32_t& r3) {
    asm volatile("ldmatrix.sync.aligned.m8n8.x4.shared.b16 {%0,%1,%2,%3}, [%4];"
                 : "=r"(r0), "=r"(r1), "=r"(r2), "=r"(r3) : "r"(addr));
}
__device__ __forceinline__ void ldmx4t(uint32_t addr, uint32_t& r0, uint32_t& r1,
                                       uint32_t& r2, uint32_t& r3) {
    asm volatile("ldmatrix.sync.aligned.m8n8.x4.trans.shared.b16 {%0,%1,%2,%3}, [%4];"
                 : "=r"(r0), "=r"(r1), "=r"(r2), "=r"(r3) : "r"(addr));
}
__device__ __forceinline__ void mma16816(float* d, const uint32_t* a, const uint32_t* b) {
    asm volatile("mma.sync.aligned.m16n8k16.row.col.f32.f16.f16.f32 "
                 "{%0,%1,%2,%3}, {%4,%5,%6,%7}, {%8,%9}, {%0,%1,%2,%3};"
                 : "+f"(d[0]), "+f"(d[1]), "+f"(d[2]), "+f"(d[3])
                 : "r"(a[0]), "r"(a[1]), "r"(a[2]), "r"(a[3]), "r"(b[0]), "r"(b[1]));
}
__device__ __forceinline__ uint32_t pack2(float x, float y) {
    __half2 h = __floats2half2_rn(x, y);
    return *(uint32_t*)&h;
}
__device__ __forceinline__ void split2(float x, float y, uint32_t& hi, uint32_t& lo) {
    __half2 h = __floats2half2_rn(x, y);
    hi = *(uint32_t*)&h;
    __half2 l2 = __floats2half2_rn(x - __low2float(h), y - __high2float(h));
    lo = *(uint32_t*)&l2;
}
__device__ __forceinline__ void cp16(uint32_t dst, const void* src) {
    asm volatile("cp.async.cg.shared.global [%0], [%1], 16;" :: "r"(dst), "l"(src));
}
__device__ __forceinline__ void cp_commit() { asm volatile("cp.async.commit_group;"); }
template<int N_> __device__ __forceinline__ void cp_wait() {
    asm volatile("cp.async.wait_group %0;" :: "n"(N_));
}
__device__ __forceinline__ float gelu_f(float x) {
    return 0.5f * x * (1.0f + erff(x * 0.70710678118654752f));
}

// ---------------- one-time conversion kernels ------------------------------
__global__ void cvt_hi(const float* __restrict__ s, hf* __restrict__ hi, int n) {
    int i = (blockIdx.x * blockDim.x + threadIdx.x) * 4;
    if (i >= n) return;
    float4 f = *(const float4*)(s + i);
    *(uint2*)(hi + i) = make_uint2(pack2(f.x, f.y), pack2(f.z, f.w));
}
__global__ void split_scale(const float* __restrict__ s, hf* __restrict__ hi,
                            hf* __restrict__ lo, int n) {
    int i = (blockIdx.x * blockDim.x + threadIdx.x) * 4;
    if (i >= n) return;
    float4 f = *(const float4*)(s + i);
    uint32_t h0, l0, h1, l1;
    split2(f.x * 64.f, f.y * 64.f, h0, l0);
    split2(f.z * 64.f, f.w * 64.f, h1, l1);
    *(uint2*)(hi + i) = make_uint2(h0, h1);
    *(uint2*)(lo + i) = make_uint2(l0, l1);
}
__global__ void repack_split_qkv(const float* __restrict__ qw,
                                 const float* __restrict__ kw,
                                 const float* __restrict__ vw) {
    int idx = blockIdx.x * blockDim.x + threadIdx.x;
    const int total = 3 * D_ * D_;
    if (idx >= total) return;
    int n = idx / D_, d = idx % D_;
    int part = n / D_, nn = n % D_;
    int h = nn / HD_, e = nn % HD_;
    const float* w = (part == 0) ? qw : (part == 1) ? kw : vw;
    float v = w[((size_t)h * D_ + d) * HD_ + e] * 64.f;
    hf hv = __float2half_rn(v);
    g_W3h[idx] = hv;
    g_W3l[idx] = __float2half_rn(v - __half2float(hv));
}

// ------------- fp16x2 HMMA GEMM-NT v3: warp tile 64x64 ---------------------
// C = oscale * Ah[M,K] * (Bh+Bl)[N,K]^T  (2 MMA passes; B pre-scaled x64).
// CTA 256(M) x 128(N), 256 thr (8 warps: 4M x 2N, warp tile 64x64), K-step 32.
// Stage 32KB: A hi-only COMPACT (2 rows per 128B row) 16KB + B hi|lo 16KB.
// 3-stage cp.async ring = 96KB. B frags reused across 4 M-subtiles ->
// 1.6x more MMA FLOPs per smem byte than v2 (smem crossbar is the roofline).
// EPI: 0 none, 1 bias+GELU, 2 bias.  OUTM: 0 hi only, 1 fp32, 2 hi+lo split.
#define G3_STAGE 32768u
#define G3_SMEM  (3*32768)   // 98304

template<int EPI, int OUTM>
__global__ void __launch_bounds__(256)
gemm_fp16(const hf* __restrict__ Ah,
          const hf* __restrict__ Bh, const hf* __restrict__ Bl,
          const float* __restrict__ bias, float oscale, float* __restrict__ C32,
          hf* __restrict__ Chi, hf* __restrict__ Clo,
          int M, int N, int K) {
    constexpr int STAGES = 3;
    extern __shared__ char smem[];
    const uint32_t sb = smem_u32(smem);
    const int tid = threadIdx.x, l = tid & 31, w = tid >> 5;
    const int n0 = blockIdx.x * 128, m0 = blockIdx.y * 256;

    // ---- A loader: 1 thr/row (256 rows), 4 x cp16 covers 32 fp16 (64B) ----
    const int ar = tid;
    const hf* aph = Ah + (size_t)(m0 + ar) * K;
    const uint32_t ad = SWZ((uint32_t)((ar >> 1) * 128 + (ar & 1) * 64));

    // ---- B loader: 2 thr/row (128 rows), 32B hi + 32B lo each ----
    const int br = tid >> 1, bc = (tid & 1) * 32;
    const hf* bph = Bh + (size_t)(n0 + br) * K + bc / 2;
    const hf* bpl = Bl + (size_t)(n0 + br) * K + bc / 2;
    const uint32_t bd0 = 16384u + SWZ((uint32_t)(br * 128 + bc));
    const uint32_t bd1 = bd0 ^ 16u;

    const int nk = K >> 5;

    // prologue: stages 0..1
#pragma unroll
    for (int s = 0; s < STAGES - 1; s++) {
        const uint32_t st = sb + (uint32_t)s * G3_STAGE;
        const int ko = s * 32;
        cp16(st + ad,         aph + ko);
        cp16(st + (ad ^ 16),  aph + ko + 8);
        cp16(st + (ad ^ 32),  aph + ko + 16);
        cp16(st + (ad ^ 48),  aph + ko + 24);
        cp16(st + bd0, bph + ko);        cp16(st + bd1, bph + ko + 8);
        cp16(st + (bd0 ^ 64), bpl + ko); cp16(st + (bd1 ^ 64), bpl + ko + 8);
        cp_commit();
    }

    // ---- mma fragment offsets (ks -> ^32, B lo -> ^64; all XOR-safe) ----
    const int warp_m = w & 3, warp_n = w >> 2;
    uint32_t aoff[4];
#pragma unroll
    for (int mi = 0; mi < 4; mi++) {
        const uint32_t rr = (uint32_t)(warp_m * 64 + mi * 16 + (l & 15));
        aoff[mi] = SWZ((rr >> 1) * 128 + (rr & 1) * 64 + ((uint32_t)(l >> 4) << 4));
    }
    uint32_t boff[4];
#pragma unroll
    for (int nj = 0; nj < 4; nj++) {
        const uint32_t rr = (uint32_t)(warp_n * 64 + nj * 16 + (((l >> 4) << 3) + (l & 7)));
        boff[nj] = 16384u + SWZ(rr * 128 + ((uint32_t)((l >> 3) & 1) << 4));
    }

    float acc[4][8][4];
#pragma unroll
    for (int mi = 0; mi < 4; mi++)
#pragma unroll
        for (int ni = 0; ni < 8; ni++)
#pragma unroll
            for (int q = 0; q < 4; q++) acc[mi][ni][q] = 0.0f;

    int s_cur = 0, s_nxt = STAGES - 1;
    for (int kb = 0; kb < nk; kb++) {
        cp_wait<STAGES - 2>();
        __syncthreads();
        if (kb + STAGES - 1 < nk) {
            const uint32_t st = sb + (uint32_t)s_nxt * G3_STAGE;
            const int ko = (kb + STAGES - 1) * 32;
            cp16(st + ad,        aph + ko);
            cp16(st + (ad ^ 16), aph + ko + 8);
            cp16(st + (ad ^ 32), aph + ko + 16);
            cp16(st + (ad ^ 48), aph + ko + 24);
            cp16(st + bd0, bph + ko);        cp16(st + bd1, bph + ko + 8);
            cp16(st + (bd0 ^ 64), bpl + ko); cp16(st + (bd1 ^ 64), bpl + ko + 8);
        }
        cp_commit();
        if (++s_nxt == STAGES) s_nxt = 0;

        const uint32_t st = sb + (uint32_t)s_cur * G3_STAGE;
        if (++s_cur == STAGES) s_cur = 0;
#pragma unroll
        for (int ks = 0; ks < 2; ks++) {
            const uint32_t kx = (uint32_t)(ks * 32);
            uint32_t ah[4][4];
#pragma unroll
            for (int mi = 0; mi < 4; mi++)
                ldmx4(st + (aoff[mi] ^ kx), ah[mi][0], ah[mi][1], ah[mi][2], ah[mi][3]);
#pragma unroll
            for (int nj = 0; nj < 4; nj++) {
                uint32_t bh2[2][2], bl2[2][2];
                ldmx4(st + (boff[nj] ^ kx),
                      bh2[0][0], bh2[0][1], bh2[1][0], bh2[1][1]);
                ldmx4(st + (boff[nj] ^ kx ^ 64),
                      bl2[0][0], bl2[0][1], bl2[1][0], bl2[1][1]);
#pragma unroll
                for (int mi = 0; mi < 4; mi++)
#pragma unroll
                    for (int t = 0; t < 2; t++) {
                        mma16816(acc[mi][2 * nj + t], ah[mi], bh2[t]);
                        mma16816(acc[mi][2 * nj + t], ah[mi], bl2[t]);
                    }
            }
        }
    }

    // ---- epilogue ----
    const int mrow0 = m0 + warp_m * 64 + (l >> 2);
    const int ncol0 = n0 + warp_n * 64 + (l & 3) * 2;
#pragma unroll
    for (int mi = 0; mi < 4; mi++)
#pragma unroll
        for (int hf2 = 0; hf2 < 2; hf2++) {
            const int row = mrow0 + mi * 16 + hf2 * 8;
#pragma unroll
            for (int ni = 0; ni < 8; ni++) {
                const int col = ncol0 + ni * 8;
                float v0 = acc[mi][ni][hf2 * 2 + 0] * oscale;
                float v1 = acc[mi][ni][hf2 * 2 + 1] * oscale;
                if (EPI >= 1) { v0 += bias[col]; v1 += bias[col + 1]; }
                if (EPI == 1) { v0 = gelu_f(v0); v1 = gelu_f(v1); }
                if (OUTM == 1) {
                    *(float2*)(C32 + (size_t)row * N + col) = make_float2(v0, v1);
                } else if (OUTM == 0) {
                    *(uint32_t*)(Chi + (size_t)row * N + col) = pack2(v0, v1);
                } else {
                    uint32_t h, l2;
                    split2(v0, v1, h, l2);
                    *(uint32_t*)(Chi + (size_t)row * N + col) = h;
                    *(uint32_t*)(Clo + (size_t)row * N + col) = l2;
                }
            }
        }
}

// ---------------- tensor-core flash attention (fp16x2) ---------------------
// CTA: 256 threads (8 warps), 128 queries. 64-key tiles, 3-stage cp.async ring.
// stage = [K hi 8KB | K lo 8KB | V hi 8KB | V lo 8KB] = 32KB.
// Q/K/V are stored x16; scores scale = 0.125/256, O scale = 1/16.
#define AS_STAGE 32768
#define ATT_SMEM (3*AS_STAGE)   // 98304

__global__ void __launch_bounds__(256)
attn_mma(const hf* __restrict__ Qh, const hf* __restrict__ Ql,
         hf* __restrict__ Ohi) {
    extern __shared__ char smem[];
    const uint32_t sb = smem_u32(smem);
    const int tid = threadIdx.x, l = tid & 31, w = tid >> 5;
    const int bh = blockIdx.y, b = bh / H_, h = bh % H_;
    const int q0 = blockIdx.x * 128;
    const size_t rs = 3 * D_;

    const hf* qbh = Qh + (size_t)b * S_ * rs + h * HD_;
    const hf* qbl = Ql + (size_t)b * S_ * rs + h * HD_;

    // ---- loader: 128 thr -> K (hi+lo), 128 thr -> V (hi+lo); 2 thr/row ----
    const int mat = tid >> 7, t7 = tid & 127;
    const int r = t7 >> 1, half = t7 & 1;
    const hf* lbh = qbh + (size_t)(mat + 1) * D_ + (size_t)r * rs + half * 32;
    const hf* lbl = qbl + (size_t)(mat + 1) * D_ + (size_t)r * rs + half * 32;
    const uint32_t blk = (uint32_t)mat * 16384u;
    uint32_t off[4];
#pragma unroll
    for (int j = 0; j < 4; j++)
        off[j] = SWZ((uint32_t)(r * 128 + half * 64 + j * 16));

    // prologue: tiles 0,1
#pragma unroll
    for (int s = 0; s < 2; s++) {
        uint32_t st = sb + (uint32_t)s * AS_STAGE;
        const hf* ph = lbh + (size_t)s * 64 * rs;
        const hf* pl = lbl + (size_t)s * 64 * rs;
#pragma unroll
        for (int j = 0; j < 4; j++) {
            cp16(st + blk + off[j],        ph + j * 8);
            cp16(st + blk + 8192 + off[j], pl + j * 8);
        }
        cp_commit();
    }

    // ---- Q fragments (hi only) ----
    uint32_t qhi[4][4];
    {
        const int r0 = q0 + w * 16 + (l >> 2);
        const hf* q0h = qbh + (size_t)r0 * rs;
#pragma unroll
        for (int ks = 0; ks < 4; ks++) {
            const int k = ks * 16 + 2 * (l & 3);
            qhi[ks][0] = *(const uint32_t*)(q0h + k);
            qhi[ks][1] = *(const uint32_t*)(q0h + 8 * rs + k);
            qhi[ks][2] = *(const uint32_t*)(q0h + k + 8);
            qhi[ks][3] = *(const uint32_t*)(q0h + 8 * rs + k + 8);
        }
    }

    float mrow0 = -1e30f, mrow1 = -1e30f, lsum0 = 0.f, lsum1 = 0.f;
    float oacc[8][4];
#pragma unroll
    for (int nd = 0; nd < 8; nd++)
#pragma unroll
        for (int q = 0; q < 4; q++) oacc[nd][q] = 0.f;

    for (int kt = 0; kt < S_ / 64; kt++) {
        cp_wait<1>();
        __syncthreads();
        if (kt + 2 < S_ / 64) {
            uint32_t st = sb + (uint32_t)((kt + 2) % 3) * AS_STAGE;
            const hf* ph = lbh + (size_t)(kt + 2) * 64 * rs;
            const hf* pl = lbl + (size_t)(kt + 2) * 64 * rs;
#pragma unroll
            for (int j = 0; j < 4; j++) {
                cp16(st + blk + off[j],        ph + j * 8);
                cp16(st + blk + 8192 + off[j], pl + j * 8);
            }
        }
        cp_commit();

        const uint32_t st = sb + (uint32_t)(kt % 3) * AS_STAGE;

        // ---- S = Q K^T (2 passes: Qh*Kh + Qh*Kl) ----
        float sacc[8][4];
#pragma unroll
        for (int nt = 0; nt < 8; nt++)
#pragma unroll
            for (int q = 0; q < 4; q++) sacc[nt][q] = 0.f;

#pragma unroll
        for (int ks = 0; ks < 4; ks++) {
            uint32_t bkh[8][2], bkl[8][2];
#pragma unroll
            for (int nj = 0; nj < 4; nj++) {
                uint32_t rr = (uint32_t)(nj * 16 + (((l >> 4) << 3) + (l & 7)));
                uint32_t cc = (uint32_t)(ks * 32 + (((l >> 3) & 1) << 4));
                uint32_t o = SWZ(rr * 128 + cc);
                ldmx4(st + o,        bkh[2*nj][0], bkh[2*nj][1], bkh[2*nj+1][0], bkh[2*nj+1][1]);
                ldmx4(st + 8192 + o, bkl[2*nj][0], bkl[2*nj][1], bkl[2*nj+1][0], bkl[2*nj+1][1]);
            }
#pragma unroll
            for (int nt = 0; nt < 8; nt++) {
                mma16816(sacc[nt], qhi[ks], bkh[nt]);
                mma16816(sacc[nt], qhi[ks], bkl[nt]);
            }
        }
        const float SS = 0.125f / 256.0f;
#pragma unroll
        for (int nt = 0; nt < 8; nt++)
#pragma unroll
            for (int q = 0; q < 4; q++) sacc[nt][q] *= SS;

        // ---- online softmax ----
        float mx0 = -1e30f, mx1 = -1e30f;
#pragma unroll
        for (int nt = 0; nt < 8; nt++) {
            mx0 = fmaxf(mx0, fmaxf(sacc[nt][0], sacc[nt][1]));
            mx1 = fmaxf(mx1, fmaxf(sacc[nt][2], sacc[nt][3]));
        }
        mx0 = fmaxf(mx0, __shfl_xor_sync(0xffffffffu, mx0, 1));
        mx0 = fmaxf(mx0, __shfl_xor_sync(0xffffffffu, mx0, 2));
        mx1 = fmaxf(mx1, __shfl_xor_sync(0xffffffffu, mx1, 1));
        mx1 = fmaxf(mx1, __shfl_xor_sync(0xffffffffu, mx1, 2));
        const float mn0 = fmaxf(mrow0, mx0), mn1 = fmaxf(mrow1, mx1);
        const float corr0 = __expf(mrow0 - mn0), corr1 = __expf(mrow1 - mn1);
        mrow0 = mn0; mrow1 = mn1;
        float ps0 = 0.f, ps1 = 0.f;
#pragma unroll
        for (int nt = 0; nt < 8; nt++) {
            sacc[nt][0] = __expf(sacc[nt][0] - mn0);
            sacc[nt][1] = __expf(sacc[nt][1] - mn0);
            sacc[nt][2] = __expf(sacc[nt][2] - mn1);
            sacc[nt][3] = __expf(sacc[nt][3] - mn1);
            ps0 += sacc[nt][0] + sacc[nt][1];
            ps1 += sacc[nt][2] + sacc[nt][3];
        }
        ps0 += __shfl_xor_sync(0xffffffffu, ps0, 1);
        ps0 += __shfl_xor_sync(0xffffffffu, ps0, 2);
        ps1 += __shfl_xor_sync(0xffffffffu, ps1, 1);
        ps1 += __shfl_xor_sync(0xffffffffu, ps1, 2);
        lsum0 = lsum0 * corr0 + ps0;
        lsum1 = lsum1 * corr1 + ps1;
#pragma unroll
        for (int nd = 0; nd < 8; nd++) {
            oacc[nd][0] *= corr0; oacc[nd][1] *= corr0;
            oacc[nd][2] *= corr1; oacc[nd][3] *= corr1;
        }

        // ---- P fragments (hi only) ----
        uint32_t phi[4][4];
#pragma unroll
        for (int kv = 0; kv < 4; kv++) {
            phi[kv][0] = pack2(sacc[2*kv][0],   sacc[2*kv][1]);
            phi[kv][1] = pack2(sacc[2*kv][2],   sacc[2*kv][3]);
            phi[kv][2] = pack2(sacc[2*kv+1][0], sacc[2*kv+1][1]);
            phi[kv][3] = pack2(sacc[2*kv+1][2], sacc[2*kv+1][3]);
        }

        // ---- O += P V (2 passes: P*Vh + P*Vl) ----
#pragma unroll
        for (int kv = 0; kv < 4; kv++) {
            uint32_t vh[8][2], vl[8][2];
#pragma unroll
            for (int nd = 0; nd < 4; nd++) {
                uint32_t rr = (uint32_t)(kv * 16 + (((l >> 3) & 1) << 3) + (l & 7));
                uint32_t cc = (uint32_t)(nd * 32 + ((l >> 4) << 4));
                uint32_t o = SWZ(rr * 128 + cc);
                ldmx4t(st + 16384 + o, vh[2*nd][0], vh[2*nd][1], vh[2*nd+1][0], vh[2*nd+1][1]);
                ldmx4t(st + 24576 + o, vl[2*nd][0], vl[2*nd][1], vl[2*nd+1][0], vl[2*nd+1][1]);
            }
#pragma unroll
            for (int nd = 0; nd < 8; nd++) {
                mma16816(oacc[nd], phi[kv], vh[nd]);
                mma16816(oacc[nd], phi[kv], vl[nd]);
            }
        }
    }

    // ---- write O (hi only; undo x16 V scaling) ----
    const float il0 = 0.0625f / lsum0, il1 = 0.0625f / lsum1;
    const int row0 = q0 + w * 16 + (l >> 2);
    const int colb = h * HD_ + 2 * (l & 3);
    hf* oh0 = Ohi + (size_t)(b * S_ + row0) * D_ + colb;
    hf* oh1 = Ohi + (size_t)(b * S_ + row0 + 8) * D_ + colb;
#pragma unroll
    for (int nd = 0; nd < 8; nd++) {
        *(uint32_t*)(oh0 + nd * 8) = pack2(oacc[nd][0] * il0, oacc[nd][1] * il0);
        *(uint32_t*)(oh1 + nd * 8) = pack2(oacc[nd][2] * il1, oacc[nd][3] * il1);
    }
}

// ---------------- launch ----------------------------------------------------
extern "C" void kernel_launch(void* const* d_in, const int* in_sizes, int n_in,
                              void* d_out, int out_size) {
    const float* x    = (const float*)d_in[0];
    const float* qw   = (const float*)d_in[2];
    const float* kw   = (const float*)d_in[3];
    const float* vw   = (const float*)d_in[4];
    const float* ow   = (const float*)d_in[5];
    const float* fc1w = (const float*)d_in[6];
    const float* fc1b = (const float*)d_in[7];
    const float* fc2w = (const float*)d_in[8];
    const float* fc2b = (const float*)d_in[9];
    float* out = (float*)d_out;

    hf *xh, *W3h, *W3l, *qkvh, *qkvl, *wvh, *owh, *owl;
    hf *aoh, *f1h, *f1l, *ffh, *f2h, *f2l;
    cudaGetSymbolAddress((void**)&xh,  g_x_h);
    cudaGetSymbolAddress((void**)&W3h, g_W3h);   cudaGetSymbolAddress((void**)&W3l, g_W3l);
    cudaGetSymbolAddress((void**)&qkvh,g_qkv_h); cudaGetSymbolAddress((void**)&qkvl,g_qkv_l);
    cudaGetSymbolAddress((void**)&wvh, g_wv_h);
    cudaGetSymbolAddress((void**)&owh, g_ow_h);  cudaGetSymbolAddress((void**)&owl, g_ow_l);
    cudaGetSymbolAddress((void**)&aoh, g_ao_h);
    cudaGetSymbolAddress((void**)&f1h, g_fc1_h); cudaGetSymbolAddress((void**)&f1l, g_fc1_l);
    cudaGetSymbolAddress((void**)&ffh, g_ff_h);
    cudaGetSymbolAddress((void**)&f2h, g_fc2_h); cudaGetSymbolAddress((void**)&f2l, g_fc2_l);

    cudaFuncSetAttribute((const void*)gemm_fp16<0,2>, cudaFuncAttributeMaxDynamicSharedMemorySize, G3_SMEM);
    cudaFuncSetAttribute((const void*)gemm_fp16<0,0>, cudaFuncAttributeMaxDynamicSharedMemorySize, G3_SMEM);
    cudaFuncSetAttribute((const void*)gemm_fp16<1,0>, cudaFuncAttributeMaxDynamicSharedMemorySize, G3_SMEM);
    cudaFuncSetAttribute((const void*)gemm_fp16<2,1>, cudaFuncAttributeMaxDynamicSharedMemorySize, G3_SMEM);
    cudaFuncSetAttribute((const void*)attn_mma,       cudaFuncAttributeMaxDynamicSharedMemorySize, ATT_SMEM);

    // 0) one-time conversions
    cvt_hi<<<(M_*D_/4 + 255)/256, 256>>>(x, xh, M_*D_);
    repack_split_qkv<<<(3*D_*D_ + 255)/256, 256>>>(qw, kw, vw);
    split_scale<<<(D_*D_/4 + 255)/256, 256>>>(ow, owh, owl, D_*D_);
    split_scale<<<(F_*D_/4 + 255)/256, 256>>>(fc1w, f1h, f1l, F_*D_);
    split_scale<<<(D_*F_/4 + 255)/256, 256>>>(fc2w, f2h, f2l, D_*F_);

    // 1) fused QKV projection -> split qkv (x16 stored: oscale = 16/64 = 0.25)
    gemm_fp16<0,2><<<dim3((3*D_)/128, M_/256), 256, G3_SMEM>>>(
        xh, W3h, W3l, nullptr, 0.25f, nullptr, qkvh, qkvl, M_, 3*D_, D_);

    // 2) flash attention -> wv (hi only)
    attn_mma<<<dim3(S_/128, B_*H_), 256, ATT_SMEM>>>(qkvh, qkvl, wvh);

    // 3) O projection -> ao (hi only; oscale = 1/64)
    gemm_fp16<0,0><<<dim3(D_/128, M_/256), 256, G3_SMEM>>>(
        wvh, owh, owl, nullptr, 0.015625f, nullptr, aoh, nullptr, M_, D_, D_);

    // 4) FC1 + bias + GELU -> ff (hi only)
    gemm_fp16<1,0><<<dim3(F_/128, M_/256), 256, G3_SMEM>>>(
        aoh, f1h, f1l, fc1b, 0.015625f, nullptr, ffh, nullptr, M_, F_, D_);

    // 5) FC2 + bias -> fp32 output
    gemm_fp16<2,1><<<dim3(D_/128, M_/256), 256, G3_SMEM>>>(
        ffh, f2h, f2l, fc2b, 0.015625f, out, nullptr, nullptr, M_, D_, F_);
}

// round 10
// speedup vs baseline: 1.5958x; 1.5958x over previous
#include <cuda_runtime.h>
#include <cuda_fp16.h>
#include <math.h>
#include <stdint.h>

#define B_  8
#define S_  1024
#define D_  768
#define H_  12
#define F_  3072
#define HD_ 64
#define M_  (B_*S_)   // 8192 rows

typedef __half hf;

// ---------------- scratch (device globals; no allocation allowed) ----------
__device__ __align__(16) hf g_x_h [(size_t)M_*D_];
__device__ __align__(16) hf g_W3h [3*D_*D_],         g_W3l [3*D_*D_];
__device__ __align__(16) hf g_qkv_h[(size_t)M_*3*D_], g_qkv_l[(size_t)M_*3*D_];
__device__ __align__(16) hf g_wv_h[(size_t)M_*D_];
__device__ __align__(16) hf g_ow_h[D_*D_],           g_ow_l[D_*D_];
__device__ __align__(16) hf g_ao_h[(size_t)M_*D_];
__device__ __align__(16) hf g_fc1_h[F_*D_],          g_fc1_l[F_*D_];
__device__ __align__(16) hf g_ff_h[(size_t)M_*F_];
__device__ __align__(16) hf g_fc2_h[D_*F_],          g_fc2_l[D_*F_];

#define SWZ(o) ((o) ^ (((o) >> 3) & 0x70))

// ---------------- primitives ------------------------------------------------
__device__ __forceinline__ uint32_t smem_u32(const void* p) {
    uint32_t a;
    asm("{ .reg .u64 t; cvta.to.shared.u64 t, %1; cvt.u32.u64 %0, t; }" : "=r"(a) : "l"(p));
    return a;
}
__device__ __forceinline__ void ldmx4(uint32_t addr, uint32_t& r0, uint32_t& r1,
                                      uint32_t& r2, uint32_t& r3) {
    asm volatile("ldmatrix.sync.aligned.m8n8.x4.shared.b16 {%0,%1,%2,%3}, [%4];"
                 : "=r"(r0), "=r"(r1), "=r"(r2), "=r"(r3) : "r"(addr));
}
__device__ __forceinline__ void ldmx4t(uint32_t addr, uint32_t& r0, uint32_t& r1,
                                       uint32_t& r2, uint32_t& r3) {
    asm volatile("ldmatrix.sync.aligned.m8n8.x4.trans.shared.b16 {%0,%1,%2,%3}, [%4];"
                 : "=r"(r0), "=r"(r1), "=r"(r2), "=r"(r3) : "r"(addr));
}
__device__ __forceinline__ void mma16816(float* d, const uint32_t* a, const uint32_t* b) {
    asm volatile("mma.sync.aligned.m16n8k16.row.col.f32.f16.f16.f32 "
                 "{%0,%1,%2,%3}, {%4,%5,%6,%7}, {%8,%9}, {%0,%1,%2,%3};"
                 : "+f"(d[0]), "+f"(d[1]), "+f"(d[2]), "+f"(d[3])
                 : "r"(a[0]), "r"(a[1]), "r"(a[2]), "r"(a[3]), "r"(b[0]), "r"(b[1]));
}
__device__ __forceinline__ uint32_t pack2(float x, float y) {
    __half2 h = __floats2half2_rn(x, y);
    return *(uint32_t*)&h;
}
__device__ __forceinline__ void split2(float x, float y, uint32_t& hi, uint32_t& lo) {
    __half2 h = __floats2half2_rn(x, y);
    hi = *(uint32_t*)&h;
    __half2 l2 = __floats2half2_rn(x - __low2float(h), y - __high2float(h));
    lo = *(uint32_t*)&l2;
}
__device__ __forceinline__ void cp16(uint32_t dst, const void* src) {
    asm volatile("cp.async.cg.shared.global [%0], [%1], 16;" :: "r"(dst), "l"(src));
}
__device__ __forceinline__ void cp_commit() { asm volatile("cp.async.commit_group;"); }
template<int N_> __device__ __forceinline__ void cp_wait() {
    asm volatile("cp.async.wait_group %0;" :: "n"(N_));
}
__device__ __forceinline__ float gelu_f(float x) {
    return 0.5f * x * (1.0f + erff(x * 0.70710678118654752f));
}

// ---------------- one-time conversion kernels ------------------------------
__global__ void cvt_hi(const float* __restrict__ s, hf* __restrict__ hi, int n) {
    int i = (blockIdx.x * blockDim.x + threadIdx.x) * 4;
    if (i >= n) return;
    float4 f = *(const float4*)(s + i);
    *(uint2*)(hi + i) = make_uint2(pack2(f.x, f.y), pack2(f.z, f.w));
}
__global__ void split_scale(const float* __restrict__ s, hf* __restrict__ hi,
                            hf* __restrict__ lo, int n) {
    int i = (blockIdx.x * blockDim.x + threadIdx.x) * 4;
    if (i >= n) return;
    float4 f = *(const float4*)(s + i);
    uint32_t h0, l0, h1, l1;
    split2(f.x * 64.f, f.y * 64.f, h0, l0);
    split2(f.z * 64.f, f.w * 64.f, h1, l1);
    *(uint2*)(hi + i) = make_uint2(h0, h1);
    *(uint2*)(lo + i) = make_uint2(l0, l1);
}
// hi-only x64 conversion (for single-pass weights)
__global__ void cvt_hi_scale(const float* __restrict__ s, hf* __restrict__ hi, int n) {
    int i = (blockIdx.x * blockDim.x + threadIdx.x) * 4;
    if (i >= n) return;
    float4 f = *(const float4*)(s + i);
    *(uint2*)(hi + i) = make_uint2(pack2(f.x * 64.f, f.y * 64.f),
                                   pack2(f.z * 64.f, f.w * 64.f));
}
__global__ void repack_split_qkv(const float* __restrict__ qw,
                                 const float* __restrict__ kw,
                                 const float* __restrict__ vw) {
    int idx = blockIdx.x * blockDim.x + threadIdx.x;
    const int total = 3 * D_ * D_;
    if (idx >= total) return;
    int n = idx / D_, d = idx % D_;
    int part = n / D_, nn = n % D_;
    int h = nn / HD_, e = nn % HD_;
    const float* w = (part == 0) ? qw : (part == 1) ? kw : vw;
    float v = w[((size_t)h * D_ + d) * HD_ + e] * 64.f;
    hf hv = __float2half_rn(v);
    g_W3h[idx] = hv;
    g_W3l[idx] = __float2half_rn(v - __half2float(hv));
}

// ------------- fp16 HMMA GEMM-NT (R8 base + NP passes) ---------------------
// C = oscale * Ah[M,K] * (Bh [+ Bl])[N,K]^T  (NP=2: weight hi+lo; NP=1: hi only)
// CTA 128x128, 256 thr (8 warps, 4M x 2N, warp tile 32x64), K-step 32.
// Stage 24KB: A hi-only COMPACT (2 rows / 128B smem row) 8KB + B hi|lo 16KB.
// 4-stage cp.async ring = 96KB -> 2 CTAs/SM.
// EPI: 0 none, 1 bias+GELU, 2 bias.  OUTM: 0 hi only, 1 fp32, 2 hi+lo split.
#define G2_STAGE 24576u
#define G2_SMEM  (4*24576)   // 98304

template<int EPI, int OUTM, int NP>
__global__ void __launch_bounds__(256, 2)
gemm_fp16(const hf* __restrict__ Ah,
          const hf* __restrict__ Bh, const hf* __restrict__ Bl,
          const float* __restrict__ bias, float oscale, float* __restrict__ C32,
          hf* __restrict__ Chi, hf* __restrict__ Clo,
          int M, int N, int K) {
    constexpr int STAGES = 4;
    extern __shared__ char smem[];
    const uint32_t sb = smem_u32(smem);
    const int tid = threadIdx.x, l = tid & 31, w = tid >> 5;
    const int n0 = blockIdx.x * 128, m0 = blockIdx.y * 128;

    // ---- loaders: 2 thr/row; thread covers 32B (16 fp16) of hi (and lo for B)
    const int r  = tid >> 1;
    const int cB = (tid & 1) * 32;               // byte offset within 64B hi region
    const hf* aph = Ah + (size_t)(m0 + r) * K + cB / 2;
    const hf* bph = Bh + (size_t)(n0 + r) * K + cB / 2;
    const hf* bpl = (NP == 2) ? (Bl + (size_t)(n0 + r) * K + cB / 2) : nullptr;
    // A compact: row r lives at 128B-row (r>>1), half (r&1)*64
    const uint32_t ad0 = SWZ((uint32_t)((r >> 1) * 128 + (r & 1) * 64 + cB));
    const uint32_t ad1 = SWZ((uint32_t)((r >> 1) * 128 + (r & 1) * 64 + cB + 16));
    const uint32_t bd0 = 8192u + SWZ((uint32_t)(r * 128 + cB));
    const uint32_t bd1 = 8192u + SWZ((uint32_t)(r * 128 + cB + 16));

    const int nk = K >> 5;

    // prologue: stages 0..2
#pragma unroll
    for (int s = 0; s < STAGES - 1; s++) {
        const uint32_t st = sb + (uint32_t)s * G2_STAGE;
        const int ko = s * 32;
        cp16(st + ad0, aph + ko);        cp16(st + ad1, aph + ko + 8);
        cp16(st + bd0, bph + ko);        cp16(st + bd1, bph + ko + 8);
        if (NP == 2) {
            cp16(st + (bd0 ^ 64), bpl + ko); cp16(st + (bd1 ^ 64), bpl + ko + 8);
        }
        cp_commit();
    }

    // ---- mma fragment offsets (ks -> ^32, B lo -> ^64; all XOR-safe) ----
    const int warp_m = w & 3, warp_n = w >> 2;
    uint32_t aoff[2];
#pragma unroll
    for (int mi = 0; mi < 2; mi++) {
        const uint32_t rr = (uint32_t)(warp_m * 32 + mi * 16 + (l & 15));
        aoff[mi] = SWZ((rr >> 1) * 128 + (rr & 1) * 64 + ((uint32_t)(l >> 4) << 4));
    }
    uint32_t boff[4];
#pragma unroll
    for (int nj = 0; nj < 4; nj++) {
        const uint32_t rr = (uint32_t)(warp_n * 64 + nj * 16 + (((l >> 4) << 3) + (l & 7)));
        boff[nj] = 8192u + SWZ(rr * 128 + ((uint32_t)((l >> 3) & 1) << 4));
    }

    float acc[2][8][4];
#pragma unroll
    for (int mi = 0; mi < 2; mi++)
#pragma unroll
        for (int ni = 0; ni < 8; ni++)
#pragma unroll
            for (int q = 0; q < 4; q++) acc[mi][ni][q] = 0.0f;

    int s_cur = 0, s_nxt = STAGES - 1;
    for (int kb = 0; kb < nk; kb++) {
        cp_wait<STAGES - 2>();
        __syncthreads();
        if (kb + STAGES - 1 < nk) {
            const uint32_t st = sb + (uint32_t)s_nxt * G2_STAGE;
            const int ko = (kb + STAGES - 1) * 32;
            cp16(st + ad0, aph + ko);        cp16(st + ad1, aph + ko + 8);
            cp16(st + bd0, bph + ko);        cp16(st + bd1, bph + ko + 8);
            if (NP == 2) {
                cp16(st + (bd0 ^ 64), bpl + ko); cp16(st + (bd1 ^ 64), bpl + ko + 8);
            }
        }
        cp_commit();
        if (++s_nxt == STAGES) s_nxt = 0;

        const uint32_t st = sb + (uint32_t)s_cur * G2_STAGE;
        if (++s_cur == STAGES) s_cur = 0;
#pragma unroll
        for (int ks = 0; ks < 2; ks++) {
            const uint32_t kx = (uint32_t)(ks * 32);
            uint32_t ah[2][4];
#pragma unroll
            for (int mi = 0; mi < 2; mi++)
                ldmx4(st + (aoff[mi] ^ kx), ah[mi][0], ah[mi][1], ah[mi][2], ah[mi][3]);
#pragma unroll
            for (int nj = 0; nj < 4; nj++) {
                uint32_t bh2[2][2];
                ldmx4(st + (boff[nj] ^ kx),
                      bh2[0][0], bh2[0][1], bh2[1][0], bh2[1][1]);
                if (NP == 2) {
                    uint32_t bl2[2][2];
                    ldmx4(st + (boff[nj] ^ kx ^ 64),
                          bl2[0][0], bl2[0][1], bl2[1][0], bl2[1][1]);
#pragma unroll
                    for (int mi = 0; mi < 2; mi++)
#pragma unroll
                        for (int t = 0; t < 2; t++) {
                            mma16816(acc[mi][2 * nj + t], ah[mi], bh2[t]);
                            mma16816(acc[mi][2 * nj + t], ah[mi], bl2[t]);
                        }
                } else {
#pragma unroll
                    for (int mi = 0; mi < 2; mi++)
#pragma unroll
                        for (int t = 0; t < 2; t++)
                            mma16816(acc[mi][2 * nj + t], ah[mi], bh2[t]);
                }
            }
        }
    }

    // ---- epilogue ----
    const int mrow0 = m0 + warp_m * 32 + (l >> 2);
    const int ncol0 = n0 + warp_n * 64 + (l & 3) * 2;
#pragma unroll
    for (int mi = 0; mi < 2; mi++)
#pragma unroll
        for (int hf2 = 0; hf2 < 2; hf2++) {
            const int row = mrow0 + mi * 16 + hf2 * 8;
#pragma unroll
            for (int ni = 0; ni < 8; ni++) {
                const int col = ncol0 + ni * 8;
                float v0 = acc[mi][ni][hf2 * 2 + 0] * oscale;
                float v1 = acc[mi][ni][hf2 * 2 + 1] * oscale;
                if (EPI >= 1) { v0 += bias[col]; v1 += bias[col + 1]; }
                if (EPI == 1) { v0 = gelu_f(v0); v1 = gelu_f(v1); }
                if (OUTM == 1) {
                    *(float2*)(C32 + (size_t)row * N + col) = make_float2(v0, v1);
                } else if (OUTM == 0) {
                    *(uint32_t*)(Chi + (size_t)row * N + col) = pack2(v0, v1);
                } else {
                    uint32_t h, l2;
                    split2(v0, v1, h, l2);
                    *(uint32_t*)(Chi + (size_t)row * N + col) = h;
                    *(uint32_t*)(Clo + (size_t)row * N + col) = l2;
                }
            }
        }
}

// ---------------- tensor-core flash attention (fp16x2) ---------------------
// CTA: 256 threads (8 warps), 128 queries. 64-key tiles, 3-stage cp.async ring.
// stage = [K hi 8KB | K lo 8KB | V hi 8KB | V lo 8KB] = 32KB.
// Q/K/V are stored x16; scores scale = 0.125/256, O scale = 1/16.
#define AS_STAGE 32768
#define ATT_SMEM (3*AS_STAGE)   // 98304

__global__ void __launch_bounds__(256)
attn_mma(const hf* __restrict__ Qh, const hf* __restrict__ Ql,
         hf* __restrict__ Ohi) {
    extern __shared__ char smem[];
    const uint32_t sb = smem_u32(smem);
    const int tid = threadIdx.x, l = tid & 31, w = tid >> 5;
    const int bh = blockIdx.y, b = bh / H_, h = bh % H_;
    const int q0 = blockIdx.x * 128;
    const size_t rs = 3 * D_;

    const hf* qbh = Qh + (size_t)b * S_ * rs + h * HD_;
    const hf* qbl = Ql + (size_t)b * S_ * rs + h * HD_;

    // ---- loader: 128 thr -> K (hi+lo), 128 thr -> V (hi+lo); 2 thr/row ----
    const int mat = tid >> 7, t7 = tid & 127;
    const int r = t7 >> 1, half = t7 & 1;
    const hf* lbh = qbh + (size_t)(mat + 1) * D_ + (size_t)r * rs + half * 32;
    const hf* lbl = qbl + (size_t)(mat + 1) * D_ + (size_t)r * rs + half * 32;
    const uint32_t blk = (uint32_t)mat * 16384u;
    uint32_t off[4];
#pragma unroll
    for (int j = 0; j < 4; j++)
        off[j] = SWZ((uint32_t)(r * 128 + half * 64 + j * 16));

    // prologue: tiles 0,1
#pragma unroll
    for (int s = 0; s < 2; s++) {
        uint32_t st = sb + (uint32_t)s * AS_STAGE;
        const hf* ph = lbh + (size_t)s * 64 * rs;
        const hf* pl = lbl + (size_t)s * 64 * rs;
#pragma unroll
        for (int j = 0; j < 4; j++) {
            cp16(st + blk + off[j],        ph + j * 8);
            cp16(st + blk + 8192 + off[j], pl + j * 8);
        }
        cp_commit();
    }

    // ---- Q fragments (hi only) ----
    uint32_t qhi[4][4];
    {
        const int r0 = q0 + w * 16 + (l >> 2);
        const hf* q0h = qbh + (size_t)r0 * rs;
#pragma unroll
        for (int ks = 0; ks < 4; ks++) {
            const int k = ks * 16 + 2 * (l & 3);
            qhi[ks][0] = *(const uint32_t*)(q0h + k);
            qhi[ks][1] = *(const uint32_t*)(q0h + 8 * rs + k);
            qhi[ks][2] = *(const uint32_t*)(q0h + k + 8);
            qhi[ks][3] = *(const uint32_t*)(q0h + 8 * rs + k + 8);
        }
    }

    float mrow0 = -1e30f, mrow1 = -1e30f, lsum0 = 0.f, lsum1 = 0.f;
    float oacc[8][4];
#pragma unroll
    for (int nd = 0; nd < 8; nd++)
#pragma unroll
        for (int q = 0; q < 4; q++) oacc[nd][q] = 0.f;

    for (int kt = 0; kt < S_ / 64; kt++) {
        cp_wait<1>();
        __syncthreads();
        if (kt + 2 < S_ / 64) {
            uint32_t st = sb + (uint32_t)((kt + 2) % 3) * AS_STAGE;
            const hf* ph = lbh + (size_t)(kt + 2) * 64 * rs;
            const hf* pl = lbl + (size_t)(kt + 2) * 64 * rs;
#pragma unroll
            for (int j = 0; j < 4; j++) {
                cp16(st + blk + off[j],        ph + j * 8);
                cp16(st + blk + 8192 + off[j], pl + j * 8);
            }
        }
        cp_commit();

        const uint32_t st = sb + (uint32_t)(kt % 3) * AS_STAGE;

        // ---- S = Q K^T (2 passes: Qh*Kh + Qh*Kl) ----
        float sacc[8][4];
#pragma unroll
        for (int nt = 0; nt < 8; nt++)
#pragma unroll
            for (int q = 0; q < 4; q++) sacc[nt][q] = 0.f;

#pragma unroll
        for (int ks = 0; ks < 4; ks++) {
            uint32_t bkh[8][2], bkl[8][2];
#pragma unroll
            for (int nj = 0; nj < 4; nj++) {
                uint32_t rr = (uint32_t)(nj * 16 + (((l >> 4) << 3) + (l & 7)));
                uint32_t cc = (uint32_t)(ks * 32 + (((l >> 3) & 1) << 4));
                uint32_t o = SWZ(rr * 128 + cc);
                ldmx4(st + o,        bkh[2*nj][0], bkh[2*nj][1], bkh[2*nj+1][0], bkh[2*nj+1][1]);
                ldmx4(st + 8192 + o, bkl[2*nj][0], bkl[2*nj][1], bkl[2*nj+1][0], bkl[2*nj+1][1]);
            }
#pragma unroll
            for (int nt = 0; nt < 8; nt++) {
                mma16816(sacc[nt], qhi[ks], bkh[nt]);
                mma16816(sacc[nt], qhi[ks], bkl[nt]);
            }
        }
        const float SS = 0.125f / 256.0f;
#pragma unroll
        for (int nt = 0; nt < 8; nt++)
#pragma unroll
            for (int q = 0; q < 4; q++) sacc[nt][q] *= SS;

        // ---- online softmax ----
        float mx0 = -1e30f, mx1 = -1e30f;
#pragma unroll
        for (int nt = 0; nt < 8; nt++) {
            mx0 = fmaxf(mx0, fmaxf(sacc[nt][0], sacc[nt][1]));
            mx1 = fmaxf(mx1, fmaxf(sacc[nt][2], sacc[nt][3]));
        }
        mx0 = fmaxf(mx0, __shfl_xor_sync(0xffffffffu, mx0, 1));
        mx0 = fmaxf(mx0, __shfl_xor_sync(0xffffffffu, mx0, 2));
        mx1 = fmaxf(mx1, __shfl_xor_sync(0xffffffffu, mx1, 1));
        mx1 = fmaxf(mx1, __shfl_xor_sync(0xffffffffu, mx1, 2));
        const float mn0 = fmaxf(mrow0, mx0), mn1 = fmaxf(mrow1, mx1);
        const float corr0 = __expf(mrow0 - mn0), corr1 = __expf(mrow1 - mn1);
        mrow0 = mn0; mrow1 = mn1;
        float ps0 = 0.f, ps1 = 0.f;
#pragma unroll
        for (int nt = 0; nt < 8; nt++) {
            sacc[nt][0] = __expf(sacc[nt][0] - mn0);
            sacc[nt][1] = __expf(sacc[nt][1] - mn0);
            sacc[nt][2] = __expf(sacc[nt][2] - mn1);
            sacc[nt][3] = __expf(sacc[nt][3] - mn1);
            ps0 += sacc[nt][0] + sacc[nt][1];
            ps1 += sacc[nt][2] + sacc[nt][3];
        }
        ps0 += __shfl_xor_sync(0xffffffffu, ps0, 1);
        ps0 += __shfl_xor_sync(0xffffffffu, ps0, 2);
        ps1 += __shfl_xor_sync(0xffffffffu, ps1, 1);
        ps1 += __shfl_xor_sync(0xffffffffu, ps1, 2);
        lsum0 = lsum0 * corr0 + ps0;
        lsum1 = lsum1 * corr1 + ps1;
#pragma unroll
        for (int nd = 0; nd < 8; nd++) {
            oacc[nd][0] *= corr0; oacc[nd][1] *= corr0;
            oacc[nd][2] *= corr1; oacc[nd][3] *= corr1;
        }

        // ---- P fragments (hi only) ----
        uint32_t phi[4][4];
#pragma unroll
        for (int kv = 0; kv < 4; kv++) {
            phi[kv][0] = pack2(sacc[2*kv][0],   sacc[2*kv][1]);
            phi[kv][1] = pack2(sacc[2*kv][2],   sacc[2*kv][3]);
            phi[kv][2] = pack2(sacc[2*kv+1][0], sacc[2*kv+1][1]);
            phi[kv][3] = pack2(sacc[2*kv+1][2], sacc[2*kv+1][3]);
        }

        // ---- O += P V (2 passes: P*Vh + P*Vl) ----
#pragma unroll
        for (int kv = 0; kv < 4; kv++) {
            uint32_t vh[8][2], vl[8][2];
#pragma unroll
            for (int nd = 0; nd < 4; nd++) {
                uint32_t rr = (uint32_t)(kv * 16 + (((l >> 3) & 1) << 3) + (l & 7));
                uint32_t cc = (uint32_t)(nd * 32 + ((l >> 4) << 4));
                uint32_t o = SWZ(rr * 128 + cc);
                ldmx4t(st + 16384 + o, vh[2*nd][0], vh[2*nd][1], vh[2*nd+1][0], vh[2*nd+1][1]);
                ldmx4t(st + 24576 + o, vl[2*nd][0], vl[2*nd][1], vl[2*nd+1][0], vl[2*nd+1][1]);
            }
#pragma unroll
            for (int nd = 0; nd < 8; nd++) {
                mma16816(oacc[nd], phi[kv], vh[nd]);
                mma16816(oacc[nd], phi[kv], vl[nd]);
            }
        }
    }

    // ---- write O (hi only; undo x16 V scaling) ----
    const float il0 = 0.0625f / lsum0, il1 = 0.0625f / lsum1;
    const int row0 = q0 + w * 16 + (l >> 2);
    const int colb = h * HD_ + 2 * (l & 3);
    hf* oh0 = Ohi + (size_t)(b * S_ + row0) * D_ + colb;
    hf* oh1 = Ohi + (size_t)(b * S_ + row0 + 8) * D_ + colb;
#pragma unroll
    for (int nd = 0; nd < 8; nd++) {
        *(uint32_t*)(oh0 + nd * 8) = pack2(oacc[nd][0] * il0, oacc[nd][1] * il0);
        *(uint32_t*)(oh1 + nd * 8) = pack2(oacc[nd][2] * il1, oacc[nd][3] * il1);
    }
}

// ---------------- launch ----------------------------------------------------
extern "C" void kernel_launch(void* const* d_in, const int* in_sizes, int n_in,
                              void* d_out, int out_size) {
    const float* x    = (const float*)d_in[0];
    const float* qw   = (const float*)d_in[2];
    const float* kw   = (const float*)d_in[3];
    const float* vw   = (const float*)d_in[4];
    const float* ow   = (const float*)d_in[5];
    const float* fc1w = (const float*)d_in[6];
    const float* fc1b = (const float*)d_in[7];
    const float* fc2w = (const float*)d_in[8];
    const float* fc2b = (const float*)d_in[9];
    float* out = (float*)d_out;

    hf *xh, *W3h, *W3l, *qkvh, *qkvl, *wvh, *owh, *owl;
    hf *aoh, *f1h, *ffh, *f2h;
    cudaGetSymbolAddress((void**)&xh,  g_x_h);
    cudaGetSymbolAddress((void**)&W3h, g_W3h);   cudaGetSymbolAddress((void**)&W3l, g_W3l);
    cudaGetSymbolAddress((void**)&qkvh,g_qkv_h); cudaGetSymbolAddress((void**)&qkvl,g_qkv_l);
    cudaGetSymbolAddress((void**)&wvh, g_wv_h);
    cudaGetSymbolAddress((void**)&owh, g_ow_h);  cudaGetSymbolAddress((void**)&owl, g_ow_l);
    cudaGetSymbolAddress((void**)&aoh, g_ao_h);
    cudaGetSymbolAddress((void**)&f1h, g_fc1_h);
    cudaGetSymbolAddress((void**)&ffh, g_ff_h);
    cudaGetSymbolAddress((void**)&f2h, g_fc2_h);

    cudaFuncSetAttribute((const void*)gemm_fp16<0,2,2>, cudaFuncAttributeMaxDynamicSharedMemorySize, G2_SMEM);
    cudaFuncSetAttribute((const void*)gemm_fp16<0,0,2>, cudaFuncAttributeMaxDynamicSharedMemorySize, G2_SMEM);
    cudaFuncSetAttribute((const void*)gemm_fp16<1,0,1>, cudaFuncAttributeMaxDynamicSharedMemorySize, G2_SMEM);
    cudaFuncSetAttribute((const void*)gemm_fp16<2,1,1>, cudaFuncAttributeMaxDynamicSharedMemorySize, G2_SMEM);
    cudaFuncSetAttribute((const void*)attn_mma,         cudaFuncAttributeMaxDynamicSharedMemorySize, ATT_SMEM);

    // 0) one-time conversions
    cvt_hi<<<(M_*D_/4 + 255)/256, 256>>>(x, xh, M_*D_);
    repack_split_qkv<<<(3*D_*D_ + 255)/256, 256>>>(qw, kw, vw);
    split_scale<<<(D_*D_/4 + 255)/256, 256>>>(ow, owh, owl, D_*D_);
    cvt_hi_scale<<<(F_*D_/4 + 255)/256, 256>>>(fc1w, f1h, F_*D_);
    cvt_hi_scale<<<(D_*F_/4 + 255)/256, 256>>>(fc2w, f2h, D_*F_);

    // 1) fused QKV projection -> split qkv (x16 stored: oscale = 16/64 = 0.25)
    gemm_fp16<0,2,2><<<dim3((3*D_)/128, M_/128), 256, G2_SMEM>>>(
        xh, W3h, W3l, nullptr, 0.25f, nullptr, qkvh, qkvl, M_, 3*D_, D_);

    // 2) flash attention -> wv (hi only)
    attn_mma<<<dim3(S_/128, B_*H_), 256, ATT_SMEM>>>(qkvh, qkvl, wvh);

    // 3) O projection -> ao (hi only; 2-pass weights; oscale = 1/64)
    gemm_fp16<0,0,2><<<dim3(D_/128, M_/128), 256, G2_SMEM>>>(
        wvh, owh, owl, nullptr, 0.015625f, nullptr, aoh, nullptr, M_, D_, D_);

    // 4) FC1 + bias + GELU -> ff (hi only; SINGLE-pass weights)
    gemm_fp16<1,0,1><<<dim3(F_/128, M_/128), 256, G2_SMEM>>>(
        aoh, f1h, nullptr, fc1b, 0.015625f, nullptr, ffh, nullptr, M_, F_, D_);

    // 5) FC2 + bias -> fp32 output (SINGLE-pass weights)
    gemm_fp16<2,1,1><<<dim3(D_/128, M_/128), 256, G2_SMEM>>>(
        ffh, f2h, nullptr, fc2b, 0.015625f, out, nullptr, nullptr, M_, D_, F_);
}

// round 11
// speedup vs baseline: 1.8181x; 1.1393x over previous
#include <cuda_runtime.h>
#include <cuda_fp16.h>
#include <math.h>
#include <stdint.h>

#define B_  8
#define S_  1024
#define D_  768
#define H_  12
#define F_  3072
#define HD_ 64
#define M_  (B_*S_)   // 8192 rows

typedef __half hf;

// ---------------- scratch (device globals; no allocation allowed) ----------
__device__ __align__(16) hf g_x_h [(size_t)M_*D_];
__device__ __align__(16) hf g_W3h [3*D_*D_],         g_W3l [3*D_*D_];
__device__ __align__(16) hf g_qkv_h[(size_t)M_*3*D_];
__device__ __align__(16) hf g_wv_h[(size_t)M_*D_];
__device__ __align__(16) hf g_ow_h[D_*D_],           g_ow_l[D_*D_];
__device__ __align__(16) hf g_ao_h[(size_t)M_*D_];
__device__ __align__(16) hf g_fc1_h[F_*D_];
__device__ __align__(16) hf g_ff_h[(size_t)M_*F_];
__device__ __align__(16) hf g_fc2_h[D_*F_];

#define SWZ(o) ((o) ^ (((o) >> 3) & 0x70))

// ---------------- primitives ------------------------------------------------
__device__ __forceinline__ uint32_t smem_u32(const void* p) {
    uint32_t a;
    asm("{ .reg .u64 t; cvta.to.shared.u64 t, %1; cvt.u32.u64 %0, t; }" : "=r"(a) : "l"(p));
    return a;
}
__device__ __forceinline__ void ldmx4(uint32_t addr, uint32_t& r0, uint32_t& r1,
                                      uint32_t& r2, uint32_t& r3) {
    asm volatile("ldmatrix.sync.aligned.m8n8.x4.shared.b16 {%0,%1,%2,%3}, [%4];"
                 : "=r"(r0), "=r"(r1), "=r"(r2), "=r"(r3) : "r"(addr));
}
__device__ __forceinline__ void ldmx4t(uint32_t addr, uint32_t& r0, uint32_t& r1,
                                       uint32_t& r2, uint32_t& r3) {
    asm volatile("ldmatrix.sync.aligned.m8n8.x4.trans.shared.b16 {%0,%1,%2,%3}, [%4];"
                 : "=r"(r0), "=r"(r1), "=r"(r2), "=r"(r3) : "r"(addr));
}
__device__ __forceinline__ void mma16816(float* d, const uint32_t* a, const uint32_t* b) {
    asm volatile("mma.sync.aligned.m16n8k16.row.col.f32.f16.f16.f32 "
                 "{%0,%1,%2,%3}, {%4,%5,%6,%7}, {%8,%9}, {%0,%1,%2,%3};"
                 : "+f"(d[0]), "+f"(d[1]), "+f"(d[2]), "+f"(d[3])
                 : "r"(a[0]), "r"(a[1]), "r"(a[2]), "r"(a[3]), "r"(b[0]), "r"(b[1]));
}
__device__ __forceinline__ uint32_t pack2(float x, float y) {
    __half2 h = __floats2half2_rn(x, y);
    return *(uint32_t*)&h;
}
__device__ __forceinline__ void split2(float x, float y, uint32_t& hi, uint32_t& lo) {
    __half2 h = __floats2half2_rn(x, y);
    hi = *(uint32_t*)&h;
    __half2 l2 = __floats2half2_rn(x - __low2float(h), y - __high2float(h));
    lo = *(uint32_t*)&l2;
}
__device__ __forceinline__ void cp16(uint32_t dst, const void* src) {
    asm volatile("cp.async.cg.shared.global [%0], [%1], 16;" :: "r"(dst), "l"(src));
}
__device__ __forceinline__ void cp_commit() { asm volatile("cp.async.commit_group;"); }
template<int N_> __device__ __forceinline__ void cp_wait() {
    asm volatile("cp.async.wait_group %0;" :: "n"(N_));
}
__device__ __forceinline__ float gelu_f(float x) {
    return 0.5f * x * (1.0f + erff(x * 0.70710678118654752f));
}

// ---------------- one-time conversion kernels ------------------------------
__global__ void cvt_hi(const float* __restrict__ s, hf* __restrict__ hi, int n) {
    int i = (blockIdx.x * blockDim.x + threadIdx.x) * 4;
    if (i >= n) return;
    float4 f = *(const float4*)(s + i);
    *(uint2*)(hi + i) = make_uint2(pack2(f.x, f.y), pack2(f.z, f.w));
}
__global__ void split_scale(const float* __restrict__ s, hf* __restrict__ hi,
                            hf* __restrict__ lo, int n) {
    int i = (blockIdx.x * blockDim.x + threadIdx.x) * 4;
    if (i >= n) return;
    float4 f = *(const float4*)(s + i);
    uint32_t h0, l0, h1, l1;
    split2(f.x * 64.f, f.y * 64.f, h0, l0);
    split2(f.z * 64.f, f.w * 64.f, h1, l1);
    *(uint2*)(hi + i) = make_uint2(h0, h1);
    *(uint2*)(lo + i) = make_uint2(l0, l1);
}
// hi-only x64 conversion (for single-pass weights)
__global__ void cvt_hi_scale(const float* __restrict__ s, hf* __restrict__ hi, int n) {
    int i = (blockIdx.x * blockDim.x + threadIdx.x) * 4;
    if (i >= n) return;
    float4 f = *(const float4*)(s + i);
    *(uint2*)(hi + i) = make_uint2(pack2(f.x * 64.f, f.y * 64.f),
                                   pack2(f.z * 64.f, f.w * 64.f));
}
__global__ void repack_split_qkv(const float* __restrict__ qw,
                                 const float* __restrict__ kw,
                                 const float* __restrict__ vw) {
    int idx = blockIdx.x * blockDim.x + threadIdx.x;
    const int total = 3 * D_ * D_;
    if (idx >= total) return;
    int n = idx / D_, d = idx % D_;
    int part = n / D_, nn = n % D_;
    int h = nn / HD_, e = nn % HD_;
    const float* w = (part == 0) ? qw : (part == 1) ? kw : vw;
    float v = w[((size_t)h * D_ + d) * HD_ + e] * 64.f;
    hf hv = __float2half_rn(v);
    g_W3h[idx] = hv;
    g_W3l[idx] = __float2half_rn(v - __half2float(hv));
}

// ------------- fp16 HMMA GEMM-NT (R8 base + NP passes) ---------------------
// C = oscale * Ah[M,K] * (Bh [+ Bl])[N,K]^T  (NP=2: weight hi+lo; NP=1: hi only)
// CTA 128x128, 256 thr (8 warps, 4M x 2N, warp tile 32x64), K-step 32.
// Stage 24KB: A hi-only COMPACT (2 rows / 128B smem row) 8KB + B hi|lo 16KB.
// 4-stage cp.async ring = 96KB -> 2 CTAs/SM.
// EPI: 0 none, 1 bias+GELU, 2 bias.  OUTM: 0 hi only, 1 fp32, 2 hi+lo split.
#define G2_STAGE 24576u
#define G2_SMEM  (4*24576)   // 98304

template<int EPI, int OUTM, int NP>
__global__ void __launch_bounds__(256, 2)
gemm_fp16(const hf* __restrict__ Ah,
          const hf* __restrict__ Bh, const hf* __restrict__ Bl,
          const float* __restrict__ bias, float oscale, float* __restrict__ C32,
          hf* __restrict__ Chi, hf* __restrict__ Clo,
          int M, int N, int K) {
    constexpr int STAGES = 4;
    extern __shared__ char smem[];
    const uint32_t sb = smem_u32(smem);
    const int tid = threadIdx.x, l = tid & 31, w = tid >> 5;
    const int n0 = blockIdx.x * 128, m0 = blockIdx.y * 128;

    // ---- loaders: 2 thr/row; thread covers 32B (16 fp16) of hi (and lo for B)
    const int r  = tid >> 1;
    const int cB = (tid & 1) * 32;               // byte offset within 64B hi region
    const hf* aph = Ah + (size_t)(m0 + r) * K + cB / 2;
    const hf* bph = Bh + (size_t)(n0 + r) * K + cB / 2;
    const hf* bpl = (NP == 2) ? (Bl + (size_t)(n0 + r) * K + cB / 2) : nullptr;
    // A compact: row r lives at 128B-row (r>>1), half (r&1)*64
    const uint32_t ad0 = SWZ((uint32_t)((r >> 1) * 128 + (r & 1) * 64 + cB));
    const uint32_t ad1 = SWZ((uint32_t)((r >> 1) * 128 + (r & 1) * 64 + cB + 16));
    const uint32_t bd0 = 8192u + SWZ((uint32_t)(r * 128 + cB));
    const uint32_t bd1 = 8192u + SWZ((uint32_t)(r * 128 + cB + 16));

    const int nk = K >> 5;

    // prologue: stages 0..2
#pragma unroll
    for (int s = 0; s < STAGES - 1; s++) {
        const uint32_t st = sb + (uint32_t)s * G2_STAGE;
        const int ko = s * 32;
        cp16(st + ad0, aph + ko);        cp16(st + ad1, aph + ko + 8);
        cp16(st + bd0, bph + ko);        cp16(st + bd1, bph + ko + 8);
        if (NP == 2) {
            cp16(st + (bd0 ^ 64), bpl + ko); cp16(st + (bd1 ^ 64), bpl + ko + 8);
        }
        cp_commit();
    }

    // ---- mma fragment offsets (ks -> ^32, B lo -> ^64; all XOR-safe) ----
    const int warp_m = w & 3, warp_n = w >> 2;
    uint32_t aoff[2];
#pragma unroll
    for (int mi = 0; mi < 2; mi++) {
        const uint32_t rr = (uint32_t)(warp_m * 32 + mi * 16 + (l & 15));
        aoff[mi] = SWZ((rr >> 1) * 128 + (rr & 1) * 64 + ((uint32_t)(l >> 4) << 4));
    }
    uint32_t boff[4];
#pragma unroll
    for (int nj = 0; nj < 4; nj++) {
        const uint32_t rr = (uint32_t)(warp_n * 64 + nj * 16 + (((l >> 4) << 3) + (l & 7)));
        boff[nj] = 8192u + SWZ(rr * 128 + ((uint32_t)((l >> 3) & 1) << 4));
    }

    float acc[2][8][4];
#pragma unroll
    for (int mi = 0; mi < 2; mi++)
#pragma unroll
        for (int ni = 0; ni < 8; ni++)
#pragma unroll
            for (int q = 0; q < 4; q++) acc[mi][ni][q] = 0.0f;

    int s_cur = 0, s_nxt = STAGES - 1;
    for (int kb = 0; kb < nk; kb++) {
        cp_wait<STAGES - 2>();
        __syncthreads();
        if (kb + STAGES - 1 < nk) {
            const uint32_t st = sb + (uint32_t)s_nxt * G2_STAGE;
            const int ko = (kb + STAGES - 1) * 32;
            cp16(st + ad0, aph + ko);        cp16(st + ad1, aph + ko + 8);
            cp16(st + bd0, bph + ko);        cp16(st + bd1, bph + ko + 8);
            if (NP == 2) {
                cp16(st + (bd0 ^ 64), bpl + ko); cp16(st + (bd1 ^ 64), bpl + ko + 8);
            }
        }
        cp_commit();
        if (++s_nxt == STAGES) s_nxt = 0;

        const uint32_t st = sb + (uint32_t)s_cur * G2_STAGE;
        if (++s_cur == STAGES) s_cur = 0;
#pragma unroll
        for (int ks = 0; ks < 2; ks++) {
            const uint32_t kx = (uint32_t)(ks * 32);
            uint32_t ah[2][4];
#pragma unroll
            for (int mi = 0; mi < 2; mi++)
                ldmx4(st + (aoff[mi] ^ kx), ah[mi][0], ah[mi][1], ah[mi][2], ah[mi][3]);
#pragma unroll
            for (int nj = 0; nj < 4; nj++) {
                uint32_t bh2[2][2];
                ldmx4(st + (boff[nj] ^ kx),
                      bh2[0][0], bh2[0][1], bh2[1][0], bh2[1][1]);
                if (NP == 2) {
                    uint32_t bl2[2][2];
                    ldmx4(st + (boff[nj] ^ kx ^ 64),
                          bl2[0][0], bl2[0][1], bl2[1][0], bl2[1][1]);
#pragma unroll
                    for (int mi = 0; mi < 2; mi++)
#pragma unroll
                        for (int t = 0; t < 2; t++) {
                            mma16816(acc[mi][2 * nj + t], ah[mi], bh2[t]);
                            mma16816(acc[mi][2 * nj + t], ah[mi], bl2[t]);
                        }
                } else {
#pragma unroll
                    for (int mi = 0; mi < 2; mi++)
#pragma unroll
                        for (int t = 0; t < 2; t++)
                            mma16816(acc[mi][2 * nj + t], ah[mi], bh2[t]);
                }
            }
        }
    }

    // ---- epilogue ----
    const int mrow0 = m0 + warp_m * 32 + (l >> 2);
    const int ncol0 = n0 + warp_n * 64 + (l & 3) * 2;
#pragma unroll
    for (int mi = 0; mi < 2; mi++)
#pragma unroll
        for (int hf2 = 0; hf2 < 2; hf2++) {
            const int row = mrow0 + mi * 16 + hf2 * 8;
#pragma unroll
            for (int ni = 0; ni < 8; ni++) {
                const int col = ncol0 + ni * 8;
                float v0 = acc[mi][ni][hf2 * 2 + 0] * oscale;
                float v1 = acc[mi][ni][hf2 * 2 + 1] * oscale;
                if (EPI >= 1) { v0 += bias[col]; v1 += bias[col + 1]; }
                if (EPI == 1) { v0 = gelu_f(v0); v1 = gelu_f(v1); }
                if (OUTM == 1) {
                    *(float2*)(C32 + (size_t)row * N + col) = make_float2(v0, v1);
                } else if (OUTM == 0) {
                    *(uint32_t*)(Chi + (size_t)row * N + col) = pack2(v0, v1);
                } else {
                    uint32_t h, l2;
                    split2(v0, v1, h, l2);
                    *(uint32_t*)(Chi + (size_t)row * N + col) = h;
                    *(uint32_t*)(Clo + (size_t)row * N + col) = l2;
                }
            }
        }
}

// ---------------- tensor-core flash attention (fp16, single-pass) ----------
// CTA: 256 threads (8 warps), 128 queries. 64-key tiles, 3-stage cp.async ring.
// stage = [K hi 8KB | V hi 8KB] = 16KB.
// Q/K/V are stored x16; scores scale = 0.125/256, O scale = 1/16.
#define AS_STAGE 16384
#define ATT_SMEM (3*AS_STAGE)   // 49152

__global__ void __launch_bounds__(256)
attn_mma(const hf* __restrict__ Qh, hf* __restrict__ Ohi) {
    extern __shared__ char smem[];
    const uint32_t sb = smem_u32(smem);
    const int tid = threadIdx.x, l = tid & 31, w = tid >> 5;
    const int bh = blockIdx.y, b = bh / H_, h = bh % H_;
    const int q0 = blockIdx.x * 128;
    const size_t rs = 3 * D_;

    const hf* qbh = Qh + (size_t)b * S_ * rs + h * HD_;

    // ---- loader: 128 thr -> K, 128 thr -> V; 2 thr/row, 64B each ----
    const int mat = tid >> 7, t7 = tid & 127;
    const int r = t7 >> 1, half = t7 & 1;
    const hf* lbh = qbh + (size_t)(mat + 1) * D_ + (size_t)r * rs + half * 32;
    const uint32_t blk = (uint32_t)mat * 8192u;
    uint32_t off[4];
#pragma unroll
    for (int j = 0; j < 4; j++)
        off[j] = SWZ((uint32_t)(r * 128 + half * 64 + j * 16));

    // prologue: tiles 0,1
#pragma unroll
    for (int s = 0; s < 2; s++) {
        uint32_t st = sb + (uint32_t)s * AS_STAGE;
        const hf* ph = lbh + (size_t)s * 64 * rs;
#pragma unroll
        for (int j = 0; j < 4; j++)
            cp16(st + blk + off[j], ph + j * 8);
        cp_commit();
    }

    // ---- Q fragments (hi only) ----
    uint32_t qhi[4][4];
    {
        const int r0 = q0 + w * 16 + (l >> 2);
        const hf* q0h = qbh + (size_t)r0 * rs;
#pragma unroll
        for (int ks = 0; ks < 4; ks++) {
            const int k = ks * 16 + 2 * (l & 3);
            qhi[ks][0] = *(const uint32_t*)(q0h + k);
            qhi[ks][1] = *(const uint32_t*)(q0h + 8 * rs + k);
            qhi[ks][2] = *(const uint32_t*)(q0h + k + 8);
            qhi[ks][3] = *(const uint32_t*)(q0h + 8 * rs + k + 8);
        }
    }

    float mrow0 = -1e30f, mrow1 = -1e30f, lsum0 = 0.f, lsum1 = 0.f;
    float oacc[8][4];
#pragma unroll
    for (int nd = 0; nd < 8; nd++)
#pragma unroll
        for (int q = 0; q < 4; q++) oacc[nd][q] = 0.f;

    for (int kt = 0; kt < S_ / 64; kt++) {
        cp_wait<1>();
        __syncthreads();
        if (kt + 2 < S_ / 64) {
            uint32_t st = sb + (uint32_t)((kt + 2) % 3) * AS_STAGE;
            const hf* ph = lbh + (size_t)(kt + 2) * 64 * rs;
#pragma unroll
            for (int j = 0; j < 4; j++)
                cp16(st + blk + off[j], ph + j * 8);
        }
        cp_commit();

        const uint32_t st = sb + (uint32_t)(kt % 3) * AS_STAGE;

        // ---- S = Q K^T (single pass) ----
        float sacc[8][4];
#pragma unroll
        for (int nt = 0; nt < 8; nt++)
#pragma unroll
            for (int q = 0; q < 4; q++) sacc[nt][q] = 0.f;

#pragma unroll
        for (int ks = 0; ks < 4; ks++) {
            uint32_t bkh[8][2];
#pragma unroll
            for (int nj = 0; nj < 4; nj++) {
                uint32_t rr = (uint32_t)(nj * 16 + (((l >> 4) << 3) + (l & 7)));
                uint32_t cc = (uint32_t)(ks * 32 + (((l >> 3) & 1) << 4));
                uint32_t o = SWZ(rr * 128 + cc);
                ldmx4(st + o, bkh[2*nj][0], bkh[2*nj][1], bkh[2*nj+1][0], bkh[2*nj+1][1]);
            }
#pragma unroll
            for (int nt = 0; nt < 8; nt++)
                mma16816(sacc[nt], qhi[ks], bkh[nt]);
        }
        const float SS = 0.125f / 256.0f;
#pragma unroll
        for (int nt = 0; nt < 8; nt++)
#pragma unroll
            for (int q = 0; q < 4; q++) sacc[nt][q] *= SS;

        // ---- online softmax ----
        float mx0 = -1e30f, mx1 = -1e30f;
#pragma unroll
        for (int nt = 0; nt < 8; nt++) {
            mx0 = fmaxf(mx0, fmaxf(sacc[nt][0], sacc[nt][1]));
            mx1 = fmaxf(mx1, fmaxf(sacc[nt][2], sacc[nt][3]));
        }
        mx0 = fmaxf(mx0, __shfl_xor_sync(0xffffffffu, mx0, 1));
        mx0 = fmaxf(mx0, __shfl_xor_sync(0xffffffffu, mx0, 2));
        mx1 = fmaxf(mx1, __shfl_xor_sync(0xffffffffu, mx1, 1));
        mx1 = fmaxf(mx1, __shfl_xor_sync(0xffffffffu, mx1, 2));
        const float mn0 = fmaxf(mrow0, mx0), mn1 = fmaxf(mrow1, mx1);
        const float corr0 = __expf(mrow0 - mn0), corr1 = __expf(mrow1 - mn1);
        mrow0 = mn0; mrow1 = mn1;
        float ps0 = 0.f, ps1 = 0.f;
#pragma unroll
        for (int nt = 0; nt < 8; nt++) {
            sacc[nt][0] = __expf(sacc[nt][0] - mn0);
            sacc[nt][1] = __expf(sacc[nt][1] - mn0);
            sacc[nt][2] = __expf(sacc[nt][2] - mn1);
            sacc[nt][3] = __expf(sacc[nt][3] - mn1);
            ps0 += sacc[nt][0] + sacc[nt][1];
            ps1 += sacc[nt][2] + sacc[nt][3];
        }
        ps0 += __shfl_xor_sync(0xffffffffu, ps0, 1);
        ps0 += __shfl_xor_sync(0xffffffffu, ps0, 2);
        ps1 += __shfl_xor_sync(0xffffffffu, ps1, 1);
        ps1 += __shfl_xor_sync(0xffffffffu, ps1, 2);
        lsum0 = lsum0 * corr0 + ps0;
        lsum1 = lsum1 * corr1 + ps1;
#pragma unroll
        for (int nd = 0; nd < 8; nd++) {
            oacc[nd][0] *= corr0; oacc[nd][1] *= corr0;
            oacc[nd][2] *= corr1; oacc[nd][3] *= corr1;
        }

        // ---- P fragments (hi only) ----
        uint32_t phi[4][4];
#pragma unroll
        for (int kv = 0; kv < 4; kv++) {
            phi[kv][0] = pack2(sacc[2*kv][0],   sacc[2*kv][1]);
            phi[kv][1] = pack2(sacc[2*kv][2],   sacc[2*kv][3]);
            phi[kv][2] = pack2(sacc[2*kv+1][0], sacc[2*kv+1][1]);
            phi[kv][3] = pack2(sacc[2*kv+1][2], sacc[2*kv+1][3]);
        }

        // ---- O += P V (single pass) ----
#pragma unroll
        for (int kv = 0; kv < 4; kv++) {
            uint32_t vh[8][2];
#pragma unroll
            for (int nd = 0; nd < 4; nd++) {
                uint32_t rr = (uint32_t)(kv * 16 + (((l >> 3) & 1) << 3) + (l & 7));
                uint32_t cc = (uint32_t)(nd * 32 + ((l >> 4) << 4));
                uint32_t o = SWZ(rr * 128 + cc);
                ldmx4t(st + 8192 + o, vh[2*nd][0], vh[2*nd][1], vh[2*nd+1][0], vh[2*nd+1][1]);
            }
#pragma unroll
            for (int nd = 0; nd < 8; nd++)
                mma16816(oacc[nd], phi[kv], vh[nd]);
        }
    }

    // ---- write O (hi only; undo x16 V scaling) ----
    const float il0 = 0.0625f / lsum0, il1 = 0.0625f / lsum1;
    const int row0 = q0 + w * 16 + (l >> 2);
    const int colb = h * HD_ + 2 * (l & 3);
    hf* oh0 = Ohi + (size_t)(b * S_ + row0) * D_ + colb;
    hf* oh1 = Ohi + (size_t)(b * S_ + row0 + 8) * D_ + colb;
#pragma unroll
    for (int nd = 0; nd < 8; nd++) {
        *(uint32_t*)(oh0 + nd * 8) = pack2(oacc[nd][0] * il0, oacc[nd][1] * il0);
        *(uint32_t*)(oh1 + nd * 8) = pack2(oacc[nd][2] * il1, oacc[nd][3] * il1);
    }
}

// ---------------- launch ----------------------------------------------------
extern "C" void kernel_launch(void* const* d_in, const int* in_sizes, int n_in,
                              void* d_out, int out_size) {
    const float* x    = (const float*)d_in[0];
    const float* qw   = (const float*)d_in[2];
    const float* kw   = (const float*)d_in[3];
    const float* vw   = (const float*)d_in[4];
    const float* ow   = (const float*)d_in[5];
    const float* fc1w = (const float*)d_in[6];
    const float* fc1b = (const float*)d_in[7];
    const float* fc2w = (const float*)d_in[8];
    const float* fc2b = (const float*)d_in[9];
    float* out = (float*)d_out;

    hf *xh, *W3h, *W3l, *qkvh, *wvh, *owh, *owl;
    hf *aoh, *f1h, *ffh, *f2h;
    cudaGetSymbolAddress((void**)&xh,  g_x_h);
    cudaGetSymbolAddress((void**)&W3h, g_W3h);   cudaGetSymbolAddress((void**)&W3l, g_W3l);
    cudaGetSymbolAddress((void**)&qkvh,g_qkv_h);
    cudaGetSymbolAddress((void**)&wvh, g_wv_h);
    cudaGetSymbolAddress((void**)&owh, g_ow_h);  cudaGetSymbolAddress((void**)&owl, g_ow_l);
    cudaGetSymbolAddress((void**)&aoh, g_ao_h);
    cudaGetSymbolAddress((void**)&f1h, g_fc1_h);
    cudaGetSymbolAddress((void**)&ffh, g_ff_h);
    cudaGetSymbolAddress((void**)&f2h, g_fc2_h);

    cudaFuncSetAttribute((const void*)gemm_fp16<0,0,2>, cudaFuncAttributeMaxDynamicSharedMemorySize, G2_SMEM);
    cudaFuncSetAttribute((const void*)gemm_fp16<1,0,1>, cudaFuncAttributeMaxDynamicSharedMemorySize, G2_SMEM);
    cudaFuncSetAttribute((const void*)gemm_fp16<2,1,1>, cudaFuncAttributeMaxDynamicSharedMemorySize, G2_SMEM);
    cudaFuncSetAttribute((const void*)attn_mma,         cudaFuncAttributeMaxDynamicSharedMemorySize, ATT_SMEM);

    // 0) one-time conversions
    cvt_hi<<<(M_*D_/4 + 255)/256, 256>>>(x, xh, M_*D_);
    repack_split_qkv<<<(3*D_*D_ + 255)/256, 256>>>(qw, kw, vw);
    split_scale<<<(D_*D_/4 + 255)/256, 256>>>(ow, owh, owl, D_*D_);
    cvt_hi_scale<<<(F_*D_/4 + 255)/256, 256>>>(fc1w, f1h, F_*D_);
    cvt_hi_scale<<<(D_*F_/4 + 255)/256, 256>>>(fc2w, f2h, D_*F_);

    // 1) fused QKV projection -> qkv (hi only, x16 stored: oscale = 0.25)
    gemm_fp16<0,0,2><<<dim3((3*D_)/128, M_/128), 256, G2_SMEM>>>(
        xh, W3h, W3l, nullptr, 0.25f, nullptr, qkvh, nullptr, M_, 3*D_, D_);

    // 2) flash attention (single-pass K/V) -> wv (hi only)
    attn_mma<<<dim3(S_/128, B_*H_), 256, ATT_SMEM>>>(qkvh, wvh);

    // 3) O projection -> ao (hi only; 2-pass weights; oscale = 1/64)
    gemm_fp16<0,0,2><<<dim3(D_/128, M_/128), 256, G2_SMEM>>>(
        wvh, owh, owl, nullptr, 0.015625f, nullptr, aoh, nullptr, M_, D_, D_);

    // 4) FC1 + bias + GELU -> ff (hi only; SINGLE-pass weights)
    gemm_fp16<1,0,1><<<dim3(F_/128, M_/128), 256, G2_SMEM>>>(
        aoh, f1h, nullptr, fc1b, 0.015625f, nullptr, ffh, nullptr, M_, F_, D_);

    // 5) FC2 + bias -> fp32 output (SINGLE-pass weights)
    gemm_fp16<2,1,1><<<dim3(D_/128, M_/128), 256, G2_SMEM>>>(
        ffh, f2h, nullptr, fc2b, 0.015625f, out, nullptr, nullptr, M_, D_, F_);
}

// round 13
// speedup vs baseline: 2.1282x; 1.1705x over previous
#include <cuda_runtime.h>
#include <cuda_fp16.h>
#include <math.h>
#include <stdint.h>

#define B_  8
#define S_  1024
#define D_  768
#define H_  12
#define F_  3072
#define HD_ 64
#define M_  (B_*S_)   // 8192 rows

typedef __half hf;

// ---------------- scratch (device globals; no allocation allowed) ----------
__device__ __align__(16) hf g_x_h [(size_t)M_*D_];
__device__ __align__(16) hf g_W3h [3*D_*D_];
__device__ __align__(16) hf g_qkv_h[(size_t)M_*3*D_];
__device__ __align__(16) hf g_wv_h[(size_t)M_*D_];
__device__ __align__(16) hf g_ow_h[D_*D_];
__device__ __align__(16) hf g_ao_h[(size_t)M_*D_];
__device__ __align__(16) hf g_fc1_h[F_*D_];
__device__ __align__(16) hf g_ff_h[(size_t)M_*F_];
__device__ __align__(16) hf g_fc2_h[D_*F_];

#define SWZ(o) ((o) ^ (((o) >> 3) & 0x70))

// ---------------- primitives ------------------------------------------------
__device__ __forceinline__ uint32_t smem_u32(const void* p) {
    uint32_t a;
    asm("{ .reg .u64 t; cvta.to.shared.u64 t, %1; cvt.u32.u64 %0, t; }" : "=r"(a) : "l"(p));
    return a;
}
__device__ __forceinline__ void ldmx4(uint32_t addr, uint32_t& r0, uint32_t& r1,
                                      uint32_t& r2, uint32_t& r3) {
    asm volatile("ldmatrix.sync.aligned.m8n8.x4.shared.b16 {%0,%1,%2,%3}, [%4];"
                 : "=r"(r0), "=r"(r1), "=r"(r2), "=r"(r3) : "r"(addr));
}
__device__ __forceinline__ void ldmx4t(uint32_t addr, uint32_t& r0, uint32_t& r1,
                                       uint32_t& r2, uint32_t& r3) {
    asm volatile("ldmatrix.sync.aligned.m8n8.x4.trans.shared.b16 {%0,%1,%2,%3}, [%4];"
                 : "=r"(r0), "=r"(r1), "=r"(r2), "=r"(r3) : "r"(addr));
}
__device__ __forceinline__ void mma16816(float* d, const uint32_t* a, const uint32_t* b) {
    asm volatile("mma.sync.aligned.m16n8k16.row.col.f32.f16.f16.f32 "
                 "{%0,%1,%2,%3}, {%4,%5,%6,%7}, {%8,%9}, {%0,%1,%2,%3};"
                 : "+f"(d[0]), "+f"(d[1]), "+f"(d[2]), "+f"(d[3])
                 : "r"(a[0]), "r"(a[1]), "r"(a[2]), "r"(a[3]), "r"(b[0]), "r"(b[1]));
}
__device__ __forceinline__ uint32_t pack2(float x, float y) {
    __half2 h = __floats2half2_rn(x, y);
    return *(uint32_t*)&h;
}
__device__ __forceinline__ void cp16(uint32_t dst, const void* src) {
    asm volatile("cp.async.cg.shared.global [%0], [%1], 16;" :: "r"(dst), "l"(src));
}
__device__ __forceinline__ void cp_commit() { asm volatile("cp.async.commit_group;"); }
template<int N_> __device__ __forceinline__ void cp_wait() {
    asm volatile("cp.async.wait_group %0;" :: "n"(N_));
}
__device__ __forceinline__ float gelu_f(float x) {
    return 0.5f * x * (1.0f + erff(x * 0.70710678118654752f));
}

// ---------------- one-time conversion kernels ------------------------------
__global__ void cvt_hi(const float* __restrict__ s, hf* __restrict__ hi, int n) {
    int i = (blockIdx.x * blockDim.x + threadIdx.x) * 4;
    if (i >= n) return;
    float4 f = *(const float4*)(s + i);
    *(uint2*)(hi + i) = make_uint2(pack2(f.x, f.y), pack2(f.z, f.w));
}
// hi-only x64 conversion (single-pass weights)
__global__ void cvt_hi_scale(const float* __restrict__ s, hf* __restrict__ hi, int n) {
    int i = (blockIdx.x * blockDim.x + threadIdx.x) * 4;
    if (i >= n) return;
    float4 f = *(const float4*)(s + i);
    *(uint2*)(hi + i) = make_uint2(pack2(f.x * 64.f, f.y * 64.f),
                                   pack2(f.z * 64.f, f.w * 64.f));
}
__global__ void repack_qkv_hi(const float* __restrict__ qw,
                              const float* __restrict__ kw,
                              const float* __restrict__ vw) {
    int idx = blockIdx.x * blockDim.x + threadIdx.x;
    const int total = 3 * D_ * D_;
    if (idx >= total) return;
    int n = idx / D_, d = idx % D_;
    int part = n / D_, nn = n % D_;
    int h = nn / HD_, e = nn % HD_;
    const float* w = (part == 0) ? qw : (part == 1) ? kw : vw;
    g_W3h[idx] = __float2half_rn(w[((size_t)h * D_ + d) * HD_ + e] * 64.f);
}

// ------------- fp16 HMMA GEMM-NT, single-pass weights ----------------------
// C = oscale * Ah[M,K] * Bh[N,K]^T   (B pre-scaled x64).
// CTA 128x128, 256 thr (8 warps, 4M x 2N, warp tile 32x64), K-step 32.
// Stage 24KB: A hi COMPACT (2 rows / 128B smem row) 8KB + B 16KB region.
// 4-stage cp.async ring = 96KB -> 2 CTAs/SM.
// EPI: 0 none, 1 bias+GELU, 2 bias.  OUTM: 0 hi only, 1 fp32.
#define G2_STAGE 24576u
#define G2_SMEM  (4*24576)   // 98304

template<int EPI, int OUTM>
__global__ void __launch_bounds__(256, 2)
gemm_fp16(const hf* __restrict__ Ah, const hf* __restrict__ Bh,
          const float* __restrict__ bias, float oscale, float* __restrict__ C32,
          hf* __restrict__ Chi, int M, int N, int K) {
    constexpr int STAGES = 4;
    extern __shared__ char smem[];
    const uint32_t sb = smem_u32(smem);
    const int tid = threadIdx.x, l = tid & 31, w = tid >> 5;
    const int n0 = blockIdx.x * 128, m0 = blockIdx.y * 128;

    // ---- loaders: 2 thr/row; thread covers 32B (16 fp16) ----
    const int r  = tid >> 1;
    const int cB = (tid & 1) * 32;
    const hf* aph = Ah + (size_t)(m0 + r) * K + cB / 2;
    const hf* bph = Bh + (size_t)(n0 + r) * K + cB / 2;
    const uint32_t ad0 = SWZ((uint32_t)((r >> 1) * 128 + (r & 1) * 64 + cB));
    const uint32_t ad1 = SWZ((uint32_t)((r >> 1) * 128 + (r & 1) * 64 + cB + 16));
    const uint32_t bd0 = 8192u + SWZ((uint32_t)(r * 128 + cB));
    const uint32_t bd1 = 8192u + SWZ((uint32_t)(r * 128 + cB + 16));

    const int nk = K >> 5;

    // prologue: stages 0..2
#pragma unroll
    for (int s = 0; s < STAGES - 1; s++) {
        const uint32_t st = sb + (uint32_t)s * G2_STAGE;
        const int ko = s * 32;
        cp16(st + ad0, aph + ko);  cp16(st + ad1, aph + ko + 8);
        cp16(st + bd0, bph + ko);  cp16(st + bd1, bph + ko + 8);
        cp_commit();
    }

    // ---- mma fragment offsets (ks -> ^32; XOR-safe) ----
    const int warp_m = w & 3, warp_n = w >> 2;
    uint32_t aoff[2];
#pragma unroll
    for (int mi = 0; mi < 2; mi++) {
        const uint32_t rr = (uint32_t)(warp_m * 32 + mi * 16 + (l & 15));
        aoff[mi] = SWZ((rr >> 1) * 128 + (rr & 1) * 64 + ((uint32_t)(l >> 4) << 4));
    }
    uint32_t boff[4];
#pragma unroll
    for (int nj = 0; nj < 4; nj++) {
        const uint32_t rr = (uint32_t)(warp_n * 64 + nj * 16 + (((l >> 4) << 3) + (l & 7)));
        boff[nj] = 8192u + SWZ(rr * 128 + ((uint32_t)((l >> 3) & 1) << 4));
    }

    float acc[2][8][4];
#pragma unroll
    for (int mi = 0; mi < 2; mi++)
#pragma unroll
        for (int ni = 0; ni < 8; ni++)
#pragma unroll
            for (int q = 0; q < 4; q++) acc[mi][ni][q] = 0.0f;

    int s_cur = 0, s_nxt = STAGES - 1;
    for (int kb = 0; kb < nk; kb++) {
        cp_wait<STAGES - 2>();
        __syncthreads();
        if (kb + STAGES - 1 < nk) {
            const uint32_t st = sb + (uint32_t)s_nxt * G2_STAGE;
            const int ko = (kb + STAGES - 1) * 32;
            cp16(st + ad0, aph + ko);  cp16(st + ad1, aph + ko + 8);
            cp16(st + bd0, bph + ko);  cp16(st + bd1, bph + ko + 8);
        }
        cp_commit();
        if (++s_nxt == STAGES) s_nxt = 0;

        const uint32_t st = sb + (uint32_t)s_cur * G2_STAGE;
        if (++s_cur == STAGES) s_cur = 0;
#pragma unroll
        for (int ks = 0; ks < 2; ks++) {
            const uint32_t kx = (uint32_t)(ks * 32);
            uint32_t ah[2][4];
#pragma unroll
            for (int mi = 0; mi < 2; mi++)
                ldmx4(st + (aoff[mi] ^ kx), ah[mi][0], ah[mi][1], ah[mi][2], ah[mi][3]);
#pragma unroll
            for (int nj = 0; nj < 4; nj++) {
                uint32_t bh2[2][2];
                ldmx4(st + (boff[nj] ^ kx),
                      bh2[0][0], bh2[0][1], bh2[1][0], bh2[1][1]);
#pragma unroll
                for (int mi = 0; mi < 2; mi++)
#pragma unroll
                    for (int t = 0; t < 2; t++)
                        mma16816(acc[mi][2 * nj + t], ah[mi], bh2[t]);
            }
        }
    }

    // ---- epilogue ----
    const int mrow0 = m0 + warp_m * 32 + (l >> 2);
    const int ncol0 = n0 + warp_n * 64 + (l & 3) * 2;
#pragma unroll
    for (int mi = 0; mi < 2; mi++)
#pragma unroll
        for (int hf2 = 0; hf2 < 2; hf2++) {
            const int row = mrow0 + mi * 16 + hf2 * 8;
#pragma unroll
            for (int ni = 0; ni < 8; ni++) {
                const int col = ncol0 + ni * 8;
                float v0 = acc[mi][ni][hf2 * 2 + 0] * oscale;
                float v1 = acc[mi][ni][hf2 * 2 + 1] * oscale;
                if (EPI >= 1) { v0 += bias[col]; v1 += bias[col + 1]; }
                if (EPI == 1) { v0 = gelu_f(v0); v1 = gelu_f(v1); }
                if (OUTM == 1) {
                    *(float2*)(C32 + (size_t)row * N + col) = make_float2(v0, v1);
                } else {
                    *(uint32_t*)(Chi + (size_t)row * N + col) = pack2(v0, v1);
                }
            }
        }
}

// ---------------- tensor-core flash attention (fp16, single-pass) ----------
// CTA: 256 threads (8 warps), 128 queries. 64-key tiles, 3-stage cp.async ring.
// stage = [K hi 8KB | V hi 8KB] = 16KB.
// Q/K/V are stored x16; scores scale = 0.125/256, O scale = 1/16.
#define AS_STAGE 16384
#define ATT_SMEM (3*AS_STAGE)   // 49152

__global__ void __launch_bounds__(256)
attn_mma(const hf* __restrict__ Qh, hf* __restrict__ Ohi) {
    extern __shared__ char smem[];
    const uint32_t sb = smem_u32(smem);
    const int tid = threadIdx.x, l = tid & 31, w = tid >> 5;
    const int bh = blockIdx.y, b = bh / H_, h = bh % H_;
    const int q0 = blockIdx.x * 128;
    const size_t rs = 3 * D_;

    const hf* qbh = Qh + (size_t)b * S_ * rs + h * HD_;

    // ---- loader: 128 thr -> K, 128 thr -> V; 2 thr/row, 64B each ----
    const int mat = tid >> 7, t7 = tid & 127;
    const int r = t7 >> 1, half = t7 & 1;
    const hf* lbh = qbh + (size_t)(mat + 1) * D_ + (size_t)r * rs + half * 32;
    const uint32_t blk = (uint32_t)mat * 8192u;
    uint32_t off[4];
#pragma unroll
    for (int j = 0; j < 4; j++)
        off[j] = SWZ((uint32_t)(r * 128 + half * 64 + j * 16));

    // prologue: tiles 0,1
#pragma unroll
    for (int s = 0; s < 2; s++) {
        uint32_t st = sb + (uint32_t)s * AS_STAGE;
        const hf* ph = lbh + (size_t)s * 64 * rs;
#pragma unroll
        for (int j = 0; j < 4; j++)
            cp16(st + blk + off[j], ph + j * 8);
        cp_commit();
    }

    // ---- Q fragments (hi only) ----
    uint32_t qhi[4][4];
    {
        const int r0 = q0 + w * 16 + (l >> 2);
        const hf* q0h = qbh + (size_t)r0 * rs;
#pragma unroll
        for (int ks = 0; ks < 4; ks++) {
            const int k = ks * 16 + 2 * (l & 3);
            qhi[ks][0] = *(const uint32_t*)(q0h + k);
            qhi[ks][1] = *(const uint32_t*)(q0h + 8 * rs + k);
            qhi[ks][2] = *(const uint32_t*)(q0h + k + 8);
            qhi[ks][3] = *(const uint32_t*)(q0h + 8 * rs + k + 8);
        }
    }

    float mrow0 = -1e30f, mrow1 = -1e30f, lsum0 = 0.f, lsum1 = 0.f;
    float oacc[8][4];
#pragma unroll
    for (int nd = 0; nd < 8; nd++)
#pragma unroll
        for (int q = 0; q < 4; q++) oacc[nd][q] = 0.f;

    for (int kt = 0; kt < S_ / 64; kt++) {
        cp_wait<1>();
        __syncthreads();
        if (kt + 2 < S_ / 64) {
            uint32_t st = sb + (uint32_t)((kt + 2) % 3) * AS_STAGE;
            const hf* ph = lbh + (size_t)(kt + 2) * 64 * rs;
#pragma unroll
            for (int j = 0; j < 4; j++)
                cp16(st + blk + off[j], ph + j * 8);
        }
        cp_commit();

        const uint32_t st = sb + (uint32_t)(kt % 3) * AS_STAGE;

        // ---- S = Q K^T (single pass) ----
        float sacc[8][4];
#pragma unroll
        for (int nt = 0; nt < 8; nt++)
#pragma unroll
            for (int q = 0; q < 4; q++) sacc[nt][q] = 0.f;

#pragma unroll
        for (int ks = 0; ks < 4; ks++) {
            uint32_t bkh[8][2];
#pragma unroll
            for (int nj = 0; nj < 4; nj++) {
                uint32_t rr = (uint32_t)(nj * 16 + (((l >> 4) << 3) + (l & 7)));
                uint32_t cc = (uint32_t)(ks * 32 + (((l >> 3) & 1) << 4));
                uint32_t o = SWZ(rr * 128 + cc);
                ldmx4(st + o, bkh[2*nj][0], bkh[2*nj][1], bkh[2*nj+1][0], bkh[2*nj+1][1]);
            }
#pragma unroll
            for (int nt = 0; nt < 8; nt++)
                mma16816(sacc[nt], qhi[ks], bkh[nt]);
        }
        const float SS = 0.125f / 256.0f;
#pragma unroll
        for (int nt = 0; nt < 8; nt++)
#pragma unroll
            for (int q = 0; q < 4; q++) sacc[nt][q] *= SS;

        // ---- online softmax ----
        float mx0 = -1e30f, mx1 = -1e30f;
#pragma unroll
        for (int nt = 0; nt < 8; nt++) {
            mx0 = fmaxf(mx0, fmaxf(sacc[nt][0], sacc[nt][1]));
            mx1 = fmaxf(mx1, fmaxf(sacc[nt][2], sacc[nt][3]));
        }
        mx0 = fmaxf(mx0, __shfl_xor_sync(0xffffffffu, mx0, 1));
        mx0 = fmaxf(mx0, __shfl_xor_sync(0xffffffffu, mx0, 2));
        mx1 = fmaxf(mx1, __shfl_xor_sync(0xffffffffu, mx1, 1));
        mx1 = fmaxf(mx1, __shfl_xor_sync(0xffffffffu, mx1, 2));
        const float mn0 = fmaxf(mrow0, mx0), mn1 = fmaxf(mrow1, mx1);
        const float corr0 = __expf(mrow0 - mn0), corr1 = __expf(mrow1 - mn1);
        mrow0 = mn0; mrow1 = mn1;
        float ps0 = 0.f, ps1 = 0.f;
#pragma unroll
        for (int nt = 0; nt < 8; nt++) {
            sacc[nt][0] = __expf(sacc[nt][0] - mn0);
            sacc[nt][1] = __expf(sacc[nt][1] - mn0);
            sacc[nt][2] = __expf(sacc[nt][2] - mn1);
            sacc[nt][3] = __expf(sacc[nt][3] - mn1);
            ps0 += sacc[nt][0] + sacc[nt][1];
            ps1 += sacc[nt][2] + sacc[nt][3];
        }
        ps0 += __shfl_xor_sync(0xffffffffu, ps0, 1);
        ps0 += __shfl_xor_sync(0xffffffffu, ps0, 2);
        ps1 += __shfl_xor_sync(0xffffffffu, ps1, 1);
        ps1 += __shfl_xor_sync(0xffffffffu, ps1, 2);
        lsum0 = lsum0 * corr0 + ps0;
        lsum1 = lsum1 * corr1 + ps1;
#pragma unroll
        for (int nd = 0; nd < 8; nd++) {
            oacc[nd][0] *= corr0; oacc[nd][1] *= corr0;
            oacc[nd][2] *= corr1; oacc[nd][3] *= corr1;
        }

        // ---- P fragments (hi only) ----
        uint32_t phi[4][4];
#pragma unroll
        for (int kv = 0; kv < 4; kv++) {
            phi[kv][0] = pack2(sacc[2*kv][0],   sacc[2*kv][1]);
            phi[kv][1] = pack2(sacc[2*kv][2],   sacc[2*kv][3]);
            phi[kv][2] = pack2(sacc[2*kv+1][0], sacc[2*kv+1][1]);
            phi[kv][3] = pack2(sacc[2*kv+1][2], sacc[2*kv+1][3]);
        }

        // ---- O += P V (single pass) ----
#pragma unroll
        for (int kv = 0; kv < 4; kv++) {
            uint32_t vh[8][2];
#pragma unroll
            for (int nd = 0; nd < 4; nd++) {
                uint32_t rr = (uint32_t)(kv * 16 + (((l >> 3) & 1) << 3) + (l & 7));
                uint32_t cc = (uint32_t)(nd * 32 + ((l >> 4) << 4));
                uint32_t o = SWZ(rr * 128 + cc);
                ldmx4t(st + 8192 + o, vh[2*nd][0], vh[2*nd][1], vh[2*nd+1][0], vh[2*nd+1][1]);
            }
#pragma unroll
            for (int nd = 0; nd < 8; nd++)
                mma16816(oacc[nd], phi[kv], vh[nd]);
        }
    }

    // ---- write O (hi only; undo x16 V scaling) ----
    const float il0 = 0.0625f / lsum0, il1 = 0.0625f / lsum1;
    const int row0 = q0 + w * 16 + (l >> 2);
    const int colb = h * HD_ + 2 * (l & 3);
    hf* oh0 = Ohi + (size_t)(b * S_ + row0) * D_ + colb;
    hf* oh1 = Ohi + (size_t)(b * S_ + row0 + 8) * D_ + colb;
#pragma unroll
    for (int nd = 0; nd < 8; nd++) {
        *(uint32_t*)(oh0 + nd * 8) = pack2(oacc[nd][0] * il0, oacc[nd][1] * il0);
        *(uint32_t*)(oh1 + nd * 8) = pack2(oacc[nd][2] * il1, oacc[nd][3] * il1);
    }
}

// ---------------- launch ----------------------------------------------------
extern "C" void kernel_launch(void* const* d_in, const int* in_sizes, int n_in,
                              void* d_out, int out_size) {
    const float* x    = (const float*)d_in[0];
    const float* qw   = (const float*)d_in[2];
    const float* kw   = (const float*)d_in[3];
    const float* vw   = (const float*)d_in[4];
    const float* ow   = (const float*)d_in[5];
    const float* fc1w = (const float*)d_in[6];
    const float* fc1b = (const float*)d_in[7];
    const float* fc2w = (const float*)d_in[8];
    const float* fc2b = (const float*)d_in[9];
    float* out = (float*)d_out;

    hf *xh, *W3h, *qkvh, *wvh, *owh, *aoh, *f1h, *ffh, *f2h;
    cudaGetSymbolAddress((void**)&xh,  g_x_h);
    cudaGetSymbolAddress((void**)&W3h, g_W3h);
    cudaGetSymbolAddress((void**)&qkvh,g_qkv_h);
    cudaGetSymbolAddress((void**)&wvh, g_wv_h);
    cudaGetSymbolAddress((void**)&owh, g_ow_h);
    cudaGetSymbolAddress((void**)&aoh, g_ao_h);
    cudaGetSymbolAddress((void**)&f1h, g_fc1_h);
    cudaGetSymbolAddress((void**)&ffh, g_ff_h);
    cudaGetSymbolAddress((void**)&f2h, g_fc2_h);

    cudaFuncSetAttribute((const void*)gemm_fp16<0,0>, cudaFuncAttributeMaxDynamicSharedMemorySize, G2_SMEM);
    cudaFuncSetAttribute((const void*)gemm_fp16<1,0>, cudaFuncAttributeMaxDynamicSharedMemorySize, G2_SMEM);
    cudaFuncSetAttribute((const void*)gemm_fp16<2,1>, cudaFuncAttributeMaxDynamicSharedMemorySize, G2_SMEM);
    cudaFuncSetAttribute((const void*)attn_mma,       cudaFuncAttributeMaxDynamicSharedMemorySize, ATT_SMEM);

    // 0) one-time conversions
    cvt_hi<<<(M_*D_/4 + 255)/256, 256>>>(x, xh, M_*D_);
    repack_qkv_hi<<<(3*D_*D_ + 255)/256, 256>>>(qw, kw, vw);
    cvt_hi_scale<<<(D_*D_/4 + 255)/256, 256>>>(ow, owh, D_*D_);
    cvt_hi_scale<<<(F_*D_/4 + 255)/256, 256>>>(fc1w, f1h, F_*D_);
    cvt_hi_scale<<<(D_*F_/4 + 255)/256, 256>>>(fc2w, f2h, D_*F_);

    // 1) fused QKV projection -> qkv (hi only, x16 stored: oscale = 0.25)
    gemm_fp16<0,0><<<dim3((3*D_)/128, M_/128), 256, G2_SMEM>>>(
        xh, W3h, nullptr, 0.25f, nullptr, qkvh, M_, 3*D_, D_);

    // 2) flash attention (single-pass K/V) -> wv (hi only)
    attn_mma<<<dim3(S_/128, B_*H_), 256, ATT_SMEM>>>(qkvh, wvh);

    // 3) O projection -> ao (hi only; oscale = 1/64)
    gemm_fp16<0,0><<<dim3(D_/128, M_/128), 256, G2_SMEM>>>(
        wvh, owh, nullptr, 0.015625f, nullptr, aoh, M_, D_, D_);

    // 4) FC1 + bias + GELU -> ff (hi only)
    gemm_fp16<1,0><<<dim3(F_/128, M_/128), 256, G2_SMEM>>>(
        aoh, f1h, fc1b, 0.015625f, nullptr, ffh, M_, F_, D_);

    // 5) FC2 + bias -> fp32 output
    gemm_fp16<2,1><<<dim3(D_/128, M_/128), 256, G2_SMEM>>>(
        ffh, f2h, fc2b, 0.015625f, out, nullptr, M_, D_, F_);
}